// round 13
// baseline (speedup 1.0000x reference)
#include <cuda_runtime.h>
#include <cuda_fp16.h>
#include <cstdint>

// Problem constants
#define BATCH 4
#define SEQ   2048
#define DMODEL 1024
#define NHEAD 8
#define HD    128
#define MROWS (BATCH*SEQ)        // 8192
#define DFF   4096
#define QKSCALE 0.08838834764831845f   // 1/sqrt(128)

// ---------------- scratch (no allocations allowed) ----------------
__device__ float g_tmp[(size_t)MROWS * DMODEL];
__device__ float g_mh[(size_t)MROWS * DMODEL];
__device__ float g_res1[(size_t)MROWS * DMODEL];
__device__ __half g_A16[(size_t)MROWS * DMODEL];     // v16, later LN1 fp16 out
__device__ __half g_F16[(size_t)MROWS * DFF];        // q16+k16 early, FF1 out later
__device__ __half g_W1t[(size_t)DFF * DMODEL];
__device__ __half g_W2t[(size_t)DFF * DMODEL];
__device__ __half g_Wq16[(size_t)DMODEL * DMODEL];
__device__ __half g_Wk16[(size_t)DMODEL * DMODEL];
__device__ __half g_Wv16[(size_t)DMODEL * DMODEL];
__device__ __half g_Qh[(size_t)MROWS * DMODEL];
__device__ __half g_Kh[(size_t)MROWS * DMODEL];
__device__ __half g_Vh[(size_t)MROWS * DMODEL];

// ======================= PTX helpers =======================
__device__ __forceinline__ uint32_t smem_u32(const void* p) {
    uint32_t a;
    asm("{ .reg .u64 t; cvta.to.shared.u64 t, %1; cvt.u32.u64 %0, t; }" : "=r"(a) : "l"(p));
    return a;
}
__device__ __forceinline__ void cp_async16(uint32_t saddr, const void* gaddr) {
    asm volatile("cp.async.cg.shared.global [%0], [%1], 16;" :: "r"(saddr), "l"(gaddr) : "memory");
}
#define CP_COMMIT() asm volatile("cp.async.commit_group;" ::: "memory")

__device__ __forceinline__ void ldmx4(uint32_t* r, uint32_t addr) {
    asm volatile("ldmatrix.sync.aligned.m8n8.x4.shared.b16 {%0,%1,%2,%3}, [%4];"
                 : "=r"(r[0]), "=r"(r[1]), "=r"(r[2]), "=r"(r[3]) : "r"(addr));
}
__device__ __forceinline__ void ldmx4t(uint32_t* r, uint32_t addr) {
    asm volatile("ldmatrix.sync.aligned.m8n8.x4.trans.shared.b16 {%0,%1,%2,%3}, [%4];"
                 : "=r"(r[0]), "=r"(r[1]), "=r"(r[2]), "=r"(r[3]) : "r"(addr));
}
__device__ __forceinline__ void mma_f16(float* c, const uint32_t* a,
                                        uint32_t b0, uint32_t b1) {
    asm volatile(
        "mma.sync.aligned.m16n8k16.row.col.f32.f16.f16.f32 "
        "{%0,%1,%2,%3}, {%4,%5,%6,%7}, {%8,%9}, {%0,%1,%2,%3};"
        : "+f"(c[0]), "+f"(c[1]), "+f"(c[2]), "+f"(c[3])
        : "r"(a[0]), "r"(a[1]), "r"(a[2]), "r"(a[3]), "r"(b0), "r"(b1));
}
__device__ __forceinline__ uint32_t packh2(float a, float b) {
    __half2 h = __floats2half2_rn(a, b);
    return *(uint32_t*)&h;
}

// =====================================================================
// fused conversions: inputs->fp16 AND all 5 weight transposes, ONE launch
// =====================================================================
#define N4SEG (MROWS * DMODEL / 4)     // 2M float4 per tensor
#define CONV_BLOCKS (3 * N4SEG / 256)  // 24576
#define WT_BLOCKS 11264
#define CW_BLOCKS (CONV_BLOCKS + WT_BLOCKS)

__global__ __launch_bounds__(256) void conv_wt_all(
    const float* __restrict__ x0, const float* __restrict__ x1,
    const float* __restrict__ x2,
    __half* __restrict__ o0c, __half* __restrict__ o1c, __half* __restrict__ o2c,
    const float* __restrict__ Wq, const float* __restrict__ Wk,
    const float* __restrict__ Wv, const float* __restrict__ W1,
    const float* __restrict__ W2,
    __half* __restrict__ oQ, __half* __restrict__ oK, __half* __restrict__ oV,
    __half* __restrict__ o1, __half* __restrict__ o2)
{
    __shared__ float t[32][33];
    if (blockIdx.x < CONV_BLOCKS) {
        int i = blockIdx.x * 256 + threadIdx.x;
        int seg = i / N4SEG;
        int j   = i - seg * N4SEG;
        const float* x = (seg == 0) ? x0 : (seg == 1) ? x1 : x2;
        __half* o      = (seg == 0) ? o0c : (seg == 1) ? o1c : o2c;
        float4 v = ((const float4*)x)[j];
        __half2* op = (__half2*)(o + (size_t)j * 4);
        op[0] = __floats2half2_rn(v.x, v.y);
        op[1] = __floats2half2_rn(v.z, v.w);
        return;
    }
    const int bid = blockIdx.x - CONV_BLOCKS;
    const float* W; __half* out; int K, N, l, gx;
    if (bid < 3072) {
        l = bid & 1023; gx = 32; K = DMODEL; N = DMODEL;
        int w = bid >> 10;
        W   = (w == 0) ? Wq : (w == 1) ? Wk : Wv;
        out = (w == 0) ? oQ : (w == 1) ? oK : oV;
    } else if (bid < 7168) {
        l = bid - 3072; gx = 128; K = DMODEL; N = DFF;  W = W1; out = o1;
    } else {
        l = bid - 7168; gx = 32;  K = DFF; N = DMODEL;  W = W2; out = o2;
    }
    const int bx = l % gx, by = l / gx;
    const int k0 = by * 32, n0 = bx * 32;
    int tx = threadIdx.x & 31, ty = threadIdx.x >> 5;
    #pragma unroll
    for (int i = ty; i < 32; i += 8)
        t[i][tx] = W[(size_t)(k0 + i) * N + n0 + tx];
    __syncthreads();
    #pragma unroll
    for (int i = ty; i < 32; i += 8)
        out[(size_t)(n0 + i) * K + k0 + tx] = __float2half(t[tx][i]);
}

// =====================================================================
// fp16 GEMM core: BK=64, NSTAGE=3, depth-1 prefetch, ONE barrier/chunk
// (BM=128, occ-2) — unchanged from R12
// =====================================================================
#define BM 128
#define BN 128
#define BK 64
#define ROWB 144
#define OPB  (128 * ROWB)
#define NSTAGE 3
#define STAGE16 (2 * OPB)
#define GEMM16_SMEM (NSTAGE * STAGE16)

__device__ __forceinline__ void prefetch16(
    uint32_t sbase, int stage, int c,
    const __half* A, const __half* B, int m0, int n0, int K, int tid)
{
    const int k0 = c * BK;
    const uint32_t sb = sbase + stage * STAGE16;
    #pragma unroll
    for (int t = 0; t < 4; t++) {
        int seg = tid + 256 * t;
        int row = seg >> 3;
        int sc  = seg & 7;
        uint32_t soff = row * ROWB + sc * 16;
        cp_async16(sb + soff,       A + (size_t)(m0 + row) * K + k0 + sc * 8);
        cp_async16(sb + OPB + soff, B + (size_t)(n0 + row) * K + k0 + sc * 8);
    }
}

__device__ __forceinline__ void gemm_core(
    uint32_t sbase, const __half* A, const __half* B,
    int m0, int n0, int K, int tid, int wid, int lane,
    float acc[2][8][4])
{
    const int wm = wid >> 1;
    const int wn = wid & 1;
    const int NC = K / BK;

    prefetch16(sbase, 0, 0, A, B, m0, n0, K, tid); CP_COMMIT();

    const uint32_t lrow = (lane & 15);
    const uint32_t lcol = (lane >> 4) * 16;

    int stg_i = 0, stg_n = 1;
    for (int c = 0; c < NC; c++) {
        if (c + 1 < NC) {
            prefetch16(sbase, stg_n, c + 1, A, B, m0, n0, K, tid);
            CP_COMMIT();
            asm volatile("cp.async.wait_group 1;" ::: "memory");
        } else {
            asm volatile("cp.async.wait_group 0;" ::: "memory");
        }
        __syncthreads();

        const uint32_t stg = sbase + stg_i * STAGE16;
        const uint32_t aBase = stg + (wm * 32) * ROWB + lrow * ROWB + lcol;
        const uint32_t bBase = stg + OPB + (wn * 64) * ROWB + lrow * ROWB + lcol;

        #pragma unroll
        for (int kk = 0; kk < 4; kk++) {
            const uint32_t kb = kk * 32;
            uint32_t ah[2][4];
            #pragma unroll
            for (int mt = 0; mt < 2; mt++)
                ldmx4(ah[mt], aBase + mt * 16 * ROWB + kb);
            #pragma unroll
            for (int p = 0; p < 4; p++) {
                uint32_t bh[4];
                ldmx4(bh, bBase + p * 16 * ROWB + kb);
                #pragma unroll
                for (int mt = 0; mt < 2; mt++) {
                    mma_f16(acc[mt][2*p],   ah[mt], bh[0], bh[2]);
                    mma_f16(acc[mt][2*p+1], ah[mt], bh[1], bh[3]);
                }
            }
        }
        stg_i = stg_n;
        stg_n = (stg_n == 2) ? 0 : stg_n + 1;
    }
}

// ---- z-batched QKV projection: out fp16 head-permuted [B,H,S,hd] ----
__global__ __launch_bounds__(256, 2) void gemm_proj(
    const __half* __restrict__ A0, const __half* __restrict__ A1,
    const __half* __restrict__ A2,
    const float* __restrict__ b0c, const float* __restrict__ b1c,
    const float* __restrict__ b2c,
    __half* __restrict__ o0, __half* __restrict__ o1, __half* __restrict__ o2)
{
    extern __shared__ char smem[];
    const uint32_t sbase = smem_u32(smem);
    const int tid = threadIdx.x;
    const int wid = tid >> 5, lane = tid & 31;
    const int z = blockIdx.z;
    const int m0 = blockIdx.y * BM, n0 = blockIdx.x * BN;

    const __half* A  = (z == 0) ? A0 : (z == 1) ? A1 : A2;
    const float* bias = (z == 0) ? b0c : (z == 1) ? b1c : b2c;
    __half* Ch       = (z == 0) ? o0 : (z == 1) ? o1 : o2;
    const float scale = (z == 0) ? QKSCALE : 1.0f;

    float acc[2][8][4];
    #pragma unroll
    for (int i = 0; i < 2; i++)
        #pragma unroll
        for (int j = 0; j < 8; j++)
            #pragma unroll
            for (int x = 0; x < 4; x++) acc[i][j][x] = 0.f;

    const __half* B = (z == 0) ? g_Wq16 : (z == 1) ? g_Wk16 : g_Wv16;
    gemm_core(sbase, A, B, m0, n0, DMODEL, tid, wid, lane, acc);

    const int wm = wid >> 1, wn = wid & 1;
    const int rbase = m0 + wm * 32 + (lane >> 2);
    const int cbase = n0 + wn * 64 + (lane & 3) * 2;
    #pragma unroll
    for (int mt = 0; mt < 2; mt++) {
        #pragma unroll
        for (int nt = 0; nt < 8; nt++) {
            const int col = cbase + nt * 8;
            const float bz0 = bias[col], bz1 = bias[col + 1];
            #pragma unroll
            for (int h = 0; h < 2; h++) {
                const int row = rbase + mt * 16 + h * 8;
                float v0 = (acc[mt][nt][2*h]   + bz0) * scale;
                float v1 = (acc[mt][nt][2*h+1] + bz1) * scale;
                const int b = row >> 11, s = row & (SEQ - 1);
                const int hh = col >> 7, d = col & (HD - 1);
                *(__half2*)(Ch + (((size_t)b * NHEAD + hh) * SEQ + s) * HD + d)
                    = __floats2half2_rn(v0, v1);
            }
        }
    }
}

// ---- generic FF GEMM: mode 0 f32 out, mode 1 ReLU + fp16 out ----
__global__ __launch_bounds__(256, 2) void gemm_f16(
    const __half* __restrict__ A, const __half* __restrict__ B,
    const float* __restrict__ bias, float* __restrict__ Cf,
    __half* __restrict__ Ch, int M, int N, int K, int mode)
{
    extern __shared__ char smem[];
    const uint32_t sbase = smem_u32(smem);
    const int tid = threadIdx.x;
    const int wid = tid >> 5, lane = tid & 31;
    const int m0 = blockIdx.y * BM, n0 = blockIdx.x * BN;

    float acc[2][8][4];
    #pragma unroll
    for (int i = 0; i < 2; i++)
        #pragma unroll
        for (int j = 0; j < 8; j++)
            #pragma unroll
            for (int x = 0; x < 4; x++) acc[i][j][x] = 0.f;

    gemm_core(sbase, A, B, m0, n0, K, tid, wid, lane, acc);

    const int wm = wid >> 1, wn = wid & 1;
    const int rbase = m0 + wm * 32 + (lane >> 2);
    const int cbase = n0 + wn * 64 + (lane & 3) * 2;
    #pragma unroll
    for (int mt = 0; mt < 2; mt++) {
        #pragma unroll
        for (int nt = 0; nt < 8; nt++) {
            const int col = cbase + nt * 8;
            const float bz0 = bias[col], bz1 = bias[col + 1];
            #pragma unroll
            for (int h = 0; h < 2; h++) {
                const int row = rbase + mt * 16 + h * 8;
                float v0 = acc[mt][nt][2*h]   + bz0;
                float v1 = acc[mt][nt][2*h+1] + bz1;
                if (mode == 0) {
                    float* dst = Cf + (size_t)row * N + col;
                    dst[0] = v0; dst[1] = v1;
                } else {
                    v0 = fmaxf(v0, 0.f); v1 = fmaxf(v1, 0.f);
                    *(__half2*)(Ch + (size_t)row * N + col) = __floats2half2_rn(v0, v1);
                }
            }
        }
    }
}

// =====================================================================
// fp16 flash attention: 128 thr / 4 warps / 128-q tiles (2 m-tiles per
// warp, K/V ldsm amortized 2x), occ-2, swizzled tiles, NS=2 ring.
// smem: Q 32K + 2 x 32K = 96K (x2 blocks = 192K)
// =====================================================================
#define ATHREADS 128
#define AQ 128
#define QTILE_B (128 * 256)            // 32768
#define KTILE_B (64 * 256)             // 16384
#define STAGE_SZ (2 * KTILE_B)         // 32768
#define ANSTAGE 2
#define SKBASE QTILE_B
#define ATT_SMEM (SKBASE + ANSTAGE * STAGE_SZ)   // 98304

__device__ __forceinline__ void attn_prefetch(
    uint32_t sb, int stage, int kt,
    const __half* Kgb, const __half* Vgb, int tid)
{
    #pragma unroll
    for (int t = 0; t < 16; t++) {
        int idx = tid + t * ATHREADS;     // 0..2047
        int tensor = idx >> 10;           // 0: K, 1: V
        int row = (idx >> 4) & 63;
        int c   = idx & 15;
        uint32_t rel = row * 256 + (((uint32_t)c ^ (row & 7)) << 4);
        uint32_t dst = sb + SKBASE + stage * STAGE_SZ + tensor * KTILE_B + rel;
        const __half* src = (tensor ? Vgb : Kgb) + (size_t)(kt * 64 + row) * HD + c * 8;
        cp_async16(dst, src);
    }
}

__global__ __launch_bounds__(ATHREADS, 2) void attn_mma(
    const __half* __restrict__ Qg, const __half* __restrict__ Kg,
    const __half* __restrict__ Vg, float* __restrict__ mh)
{
    extern __shared__ char smem[];
    const uint32_t sb = smem_u32(smem);
    const int tid = threadIdx.x;
    const int wid = tid >> 5, lane = tid & 31;
    const int qb = blockIdx.x;      // 16 q-tiles of 128
    const int bh = blockIdx.y;      // 32
    const int b = bh >> 3, h = bh & 7;

    // Q tile (swizzled): 128 rows x 16 segs = 2048 cp.async
    const __half* Qgb = Qg + ((size_t)bh * SEQ + qb * AQ) * HD;
    #pragma unroll
    for (int t = 0; t < 16; t++) {
        int idx = tid + t * ATHREADS;
        int row = idx >> 4, c = idx & 15;
        uint32_t rel = row * 256 + (((uint32_t)c ^ (row & 7)) << 4);
        cp_async16(sb + rel, Qgb + (size_t)row * HD + c * 8);
    }
    CP_COMMIT();
    const __half* Kgb = Kg + (size_t)bh * SEQ * HD;
    const __half* Vgb = Vg + (size_t)bh * SEQ * HD;
    attn_prefetch(sb, 0, 0, Kgb, Vgb, tid);
    CP_COMMIT();

    asm volatile("cp.async.wait_group 0;" ::: "memory");
    __syncthreads();

    const uint32_t lrow = lane & 15;
    const uint32_t hi16 = (lane >> 4) * 16;
    const uint32_t lanexor = (lrow & 7) << 4;

    // Q row bases for the 2 m-tiles (rows mt*64 + wid*16 + lrow)
    uint32_t qrowb[2];
    qrowb[0] = sb + (wid * 16 + lrow) * 256;
    qrowb[1] = sb + (64 + wid * 16 + lrow) * 256;

    float oacc[2][16][4];
    #pragma unroll
    for (int mt = 0; mt < 2; mt++)
        #pragma unroll
        for (int i = 0; i < 16; i++)
            #pragma unroll
            for (int j = 0; j < 4; j++) oacc[mt][i][j] = 0.f;
    float mm[2][2], ll[2][2];
    #pragma unroll
    for (int mt = 0; mt < 2; mt++) {
        mm[mt][0] = -1e30f; mm[mt][1] = -1e30f;
        ll[mt][0] = 0.f;    ll[mt][1] = 0.f;
    }

    for (int kt = 0; kt < 32; kt++) {
        if (kt + 1 < 32) {
            attn_prefetch(sb, (kt + 1) & 1, kt + 1, Kgb, Vgb, tid);
            CP_COMMIT();
            asm volatile("cp.async.wait_group 1;" ::: "memory");
        } else {
            asm volatile("cp.async.wait_group 0;" ::: "memory");
        }
        __syncthreads();   // stage kt&1 data ready

        const uint32_t kbase = sb + SKBASE + (kt & 1) * STAGE_SZ;
        const uint32_t vbase = kbase + KTILE_B;

        // ---- S = Q K^T for both m-tiles ----
        float sacc[2][8][4];
        #pragma unroll
        for (int mt = 0; mt < 2; mt++)
            #pragma unroll
            for (int i = 0; i < 8; i++)
                #pragma unroll
                for (int j = 0; j < 4; j++) sacc[mt][i][j] = 0.f;

        #pragma unroll
        for (int ks = 0; ks < 8; ks++) {
            const uint32_t colb = ((uint32_t)(ks * 32) + hi16) ^ lanexor;
            uint32_t qf0[4], qf1[4];
            ldmx4(qf0, qrowb[0] + colb);
            ldmx4(qf1, qrowb[1] + colb);
            #pragma unroll
            for (int p = 0; p < 4; p++) {
                uint32_t kf[4];
                ldmx4(kf, kbase + (p * 16 + lrow) * 256 + colb);
                mma_f16(sacc[0][2*p],   qf0, kf[0], kf[2]);
                mma_f16(sacc[0][2*p+1], qf0, kf[1], kf[3]);
                mma_f16(sacc[1][2*p],   qf1, kf[0], kf[2]);
                mma_f16(sacc[1][2*p+1], qf1, kf[1], kf[3]);
            }
        }

        // ---- online softmax + pack P, per m-tile ----
        uint32_t ph[2][4][4];
        #pragma unroll
        for (int mt = 0; mt < 2; mt++) {
            float mx0 = -1e30f, mx1 = -1e30f;
            #pragma unroll
            for (int n = 0; n < 8; n++) {
                mx0 = fmaxf(mx0, fmaxf(sacc[mt][n][0], sacc[mt][n][1]));
                mx1 = fmaxf(mx1, fmaxf(sacc[mt][n][2], sacc[mt][n][3]));
            }
            mx0 = fmaxf(mx0, __shfl_xor_sync(0xffffffffu, mx0, 1));
            mx0 = fmaxf(mx0, __shfl_xor_sync(0xffffffffu, mx0, 2));
            mx1 = fmaxf(mx1, __shfl_xor_sync(0xffffffffu, mx1, 1));
            mx1 = fmaxf(mx1, __shfl_xor_sync(0xffffffffu, mx1, 2));
            const float mn0 = fmaxf(mm[mt][0], mx0), mn1 = fmaxf(mm[mt][1], mx1);
            const float a0 = __expf(mm[mt][0] - mn0), a1 = __expf(mm[mt][1] - mn1);
            mm[mt][0] = mn0; mm[mt][1] = mn1;
            float sum0 = 0.f, sum1 = 0.f;
            #pragma unroll
            for (int n = 0; n < 8; n++) {
                sacc[mt][n][0] = __expf(sacc[mt][n][0] - mn0);
                sacc[mt][n][1] = __expf(sacc[mt][n][1] - mn0);
                sacc[mt][n][2] = __expf(sacc[mt][n][2] - mn1);
                sacc[mt][n][3] = __expf(sacc[mt][n][3] - mn1);
                sum0 += sacc[mt][n][0] + sacc[mt][n][1];
                sum1 += sacc[mt][n][2] + sacc[mt][n][3];
            }
            sum0 += __shfl_xor_sync(0xffffffffu, sum0, 1);
            sum0 += __shfl_xor_sync(0xffffffffu, sum0, 2);
            sum1 += __shfl_xor_sync(0xffffffffu, sum1, 1);
            sum1 += __shfl_xor_sync(0xffffffffu, sum1, 2);
            ll[mt][0] = ll[mt][0] * a0 + sum0;
            ll[mt][1] = ll[mt][1] * a1 + sum1;
            #pragma unroll
            for (int i = 0; i < 16; i++) {
                oacc[mt][i][0] *= a0; oacc[mt][i][1] *= a0;
                oacc[mt][i][2] *= a1; oacc[mt][i][3] *= a1;
            }
            #pragma unroll
            for (int t = 0; t < 4; t++) {
                ph[mt][t][0] = packh2(sacc[mt][2*t][0],   sacc[mt][2*t][1]);
                ph[mt][t][1] = packh2(sacc[mt][2*t][2],   sacc[mt][2*t][3]);
                ph[mt][t][2] = packh2(sacc[mt][2*t+1][0], sacc[mt][2*t+1][1]);
                ph[mt][t][3] = packh2(sacc[mt][2*t+1][2], sacc[mt][2*t+1][3]);
            }
        }

        // ---- O += P V (vf shared across both m-tiles) ----
        #pragma unroll
        for (int t = 0; t < 4; t++) {
            const uint32_t vrow = vbase + (t * 16 + lrow) * 256;
            #pragma unroll
            for (int g = 0; g < 8; g++) {
                uint32_t vf[4];
                ldmx4t(vf, vrow + (((uint32_t)(g * 32) + hi16) ^ lanexor));
                mma_f16(oacc[0][2*g],   ph[0][t], vf[0], vf[1]);
                mma_f16(oacc[0][2*g+1], ph[0][t], vf[2], vf[3]);
                mma_f16(oacc[1][2*g],   ph[1][t], vf[0], vf[1]);
                mma_f16(oacc[1][2*g+1], ph[1][t], vf[2], vf[3]);
            }
        }
        __syncthreads();   // stage reads done before next iter's prefetch
    }

    // ---- write O / l to mh[B,S,D] ----
    #pragma unroll
    for (int mt = 0; mt < 2; mt++) {
        const float inv0 = 1.f / ll[mt][0], inv1 = 1.f / ll[mt][1];
        const int row0 = qb * AQ + mt * 64 + wid * 16 + (lane >> 2);
        float* base0 = mh + ((size_t)b * SEQ + row0) * DMODEL + h * HD + (lane & 3) * 2;
        float* base1 = base0 + 8 * DMODEL;
        #pragma unroll
        for (int nt = 0; nt < 16; nt++) {
            *(float2*)(base0 + nt * 8) =
                make_float2(oacc[mt][nt][0] * inv0, oacc[mt][nt][1] * inv0);
            *(float2*)(base1 + nt * 8) =
                make_float2(oacc[mt][nt][2] * inv1, oacc[mt][nt][3] * inv1);
        }
    }
}

// =====================================================================
// LayerNorm (ddof=1, no eps) + residual — float4 vectorized (unchanged)
// =====================================================================
template<int F16OUT>
__global__ __launch_bounds__(256) void ln_res_k(
    const float* __restrict__ x, const float* __restrict__ res,
    float* __restrict__ out, __half* __restrict__ h16)
{
    const int D = DMODEL;
    const size_t row = blockIdx.x;
    const float* xr = x + row * D;
    const int tid = threadIdx.x;

    float4 v4 = ((const float4*)xr)[tid];
    float s  = v4.x + v4.y + v4.z + v4.w;
    float ss = fmaf(v4.x, v4.x, fmaf(v4.y, v4.y, fmaf(v4.z, v4.z, v4.w * v4.w)));

    #pragma unroll
    for (int off = 16; off > 0; off >>= 1) {
        s  += __shfl_xor_sync(0xffffffffu, s, off);
        ss += __shfl_xor_sync(0xffffffffu, ss, off);
    }
    __shared__ float sa[8], sbuf[8];
    int w = tid >> 5, l = tid & 31;
    if (l == 0) { sa[w] = s; sbuf[w] = ss; }
    __syncthreads();
    if (tid < 32) {
        s  = (l < 8) ? sa[l] : 0.f;
        ss = (l < 8) ? sbuf[l] : 0.f;
        #pragma unroll
        for (int off = 4; off > 0; off >>= 1) {
            s  += __shfl_xor_sync(0xffffffffu, s, off);
            ss += __shfl_xor_sync(0xffffffffu, ss, off);
        }
        if (l == 0) { sa[0] = s; sbuf[0] = ss; }
    }
    __syncthreads();
    s = sa[0]; ss = sbuf[0];

    float mean = s / (float)D;
    float var  = (ss - s * s / (float)D) / (float)(D - 1);
    float rstd = rsqrtf(var);

    float4 r4 = ((const float4*)(res + row * D))[tid];
    float4 o4;
    o4.x = r4.x + (v4.x - mean) * rstd;
    o4.y = r4.y + (v4.y - mean) * rstd;
    o4.z = r4.z + (v4.z - mean) * rstd;
    o4.w = r4.w + (v4.w - mean) * rstd;
    ((float4*)(out + row * D))[tid] = o4;
    if (F16OUT) {
        __half2* hp = (__half2*)(h16 + row * D + tid * 4);
        hp[0] = __floats2half2_rn(o4.x, o4.y);
        hp[1] = __floats2half2_rn(o4.z, o4.w);
    }
}

// =====================================================================
extern "C" void kernel_launch(void* const* d_in, const int* in_sizes, int n_in,
                              void* d_out, int out_size)
{
    const float* q  = (const float*)d_in[0];
    const float* k  = (const float*)d_in[1];
    const float* v  = (const float*)d_in[2];
    const float* Wq = (const float*)d_in[3];
    const float* bq = (const float*)d_in[4];
    const float* Wk = (const float*)d_in[5];
    const float* bk = (const float*)d_in[6];
    const float* Wv = (const float*)d_in[7];
    const float* bv = (const float*)d_in[8];
    const float* W1 = (const float*)d_in[9];
    const float* b1 = (const float*)d_in[10];
    const float* W2 = (const float*)d_in[11];
    const float* b2 = (const float*)d_in[12];

    float *tmp, *mh, *res1;
    __half *A16, *F16, *W1t, *W2t, *Wq16, *Wk16, *Wv16, *Qh, *Kh, *Vh;
    cudaGetSymbolAddress((void**)&tmp,  g_tmp);
    cudaGetSymbolAddress((void**)&mh,   g_mh);
    cudaGetSymbolAddress((void**)&res1, g_res1);
    cudaGetSymbolAddress((void**)&A16,  g_A16);
    cudaGetSymbolAddress((void**)&F16,  g_F16);
    cudaGetSymbolAddress((void**)&W1t,  g_W1t);
    cudaGetSymbolAddress((void**)&W2t,  g_W2t);
    cudaGetSymbolAddress((void**)&Wq16, g_Wq16);
    cudaGetSymbolAddress((void**)&Wk16, g_Wk16);
    cudaGetSymbolAddress((void**)&Wv16, g_Wv16);
    cudaGetSymbolAddress((void**)&Qh,   g_Qh);
    cudaGetSymbolAddress((void**)&Kh,   g_Kh);
    cudaGetSymbolAddress((void**)&Vh,   g_Vh);

    // q16 / k16 staged in first/second half of F16 (free until FF1 output)
    __half* v16 = A16;
    __half* q16 = F16;
    __half* k16 = F16 + (size_t)MROWS * DMODEL;

    cudaFuncSetAttribute(gemm_proj,
                         cudaFuncAttributeMaxDynamicSharedMemorySize, GEMM16_SMEM);
    cudaFuncSetAttribute(gemm_f16,
                         cudaFuncAttributeMaxDynamicSharedMemorySize, GEMM16_SMEM);
    cudaFuncSetAttribute(attn_mma,
                         cudaFuncAttributeMaxDynamicSharedMemorySize, ATT_SMEM);

    dim3 blk(256);
    dim3 gProj(DMODEL / BN, MROWS / BM, 3);   // (8, 64, 3)
    dim3 gFF1(DFF / BN, MROWS / BM);          // (32, 64)
    dim3 gFF2(DMODEL / BN, MROWS / BM);       // (8, 64)

    // all format conversions, one launch
    conv_wt_all<<<CW_BLOCKS, blk>>>(v, q, k, v16, q16, k16,
                                    Wq, Wk, Wv, W1, W2,
                                    Wq16, Wk16, Wv16, W1t, W2t);

    // Encoder calls multihead(v, q, k): Q-in=v, K-in=q, V-in=k
    gemm_proj<<<gProj, blk, GEMM16_SMEM>>>(v16, q16, k16, bq, bk, bv, Qh, Kh, Vh);

    attn_mma<<<dim3(SEQ / AQ, BATCH * NHEAD), dim3(ATHREADS), ATT_SMEM>>>(Qh, Kh, Vh, mh);

    // res1 = q + LN(mh); also emit fp16 for FF1 (A16 reused)
    ln_res_k<1><<<MROWS, blk>>>(mh, q, res1, A16);

    gemm_f16<<<gFF1, blk, GEMM16_SMEM>>>(A16, W1t, b1, nullptr, F16,
                                         MROWS, DFF, DMODEL, 1);
    gemm_f16<<<gFF2, blk, GEMM16_SMEM>>>(F16, W2t, b2, tmp, nullptr,
                                         MROWS, DMODEL, DFF, 0);

    ln_res_k<0><<<MROWS, blk>>>(tmp, res1, (float*)d_out, nullptr);
}

// round 14
// speedup vs baseline: 1.0416x; 1.0416x over previous
#include <cuda_runtime.h>
#include <cuda_fp16.h>
#include <cstdint>

// Problem constants
#define BATCH 4
#define SEQ   2048
#define DMODEL 1024
#define NHEAD 8
#define HD    128
#define MROWS (BATCH*SEQ)        // 8192
#define DFF   4096
#define QKSCALE 0.08838834764831845f   // 1/sqrt(128)

// ---------------- scratch (no allocations allowed) ----------------
__device__ float g_tmp[(size_t)MROWS * DMODEL];
__device__ float g_mh[(size_t)MROWS * DMODEL];
__device__ float g_res1[(size_t)MROWS * DMODEL];
__device__ __half g_A16[(size_t)MROWS * DMODEL];     // v16, later LN1 fp16 out
__device__ __half g_F16[(size_t)MROWS * DFF];        // q16+k16 early, FF1 out later
__device__ __half g_W1t[(size_t)DFF * DMODEL];
__device__ __half g_W2t[(size_t)DFF * DMODEL];
__device__ __half g_Wq16[(size_t)DMODEL * DMODEL];
__device__ __half g_Wk16[(size_t)DMODEL * DMODEL];
__device__ __half g_Wv16[(size_t)DMODEL * DMODEL];
__device__ __half g_Qh[(size_t)MROWS * DMODEL];
__device__ __half g_Kh[(size_t)MROWS * DMODEL];
__device__ __half g_Vh[(size_t)MROWS * DMODEL];

// ======================= PTX helpers =======================
__device__ __forceinline__ uint32_t smem_u32(const void* p) {
    uint32_t a;
    asm("{ .reg .u64 t; cvta.to.shared.u64 t, %1; cvt.u32.u64 %0, t; }" : "=r"(a) : "l"(p));
    return a;
}
__device__ __forceinline__ void cp_async16(uint32_t saddr, const void* gaddr) {
    asm volatile("cp.async.cg.shared.global [%0], [%1], 16;" :: "r"(saddr), "l"(gaddr) : "memory");
}
#define CP_COMMIT() asm volatile("cp.async.commit_group;" ::: "memory")

__device__ __forceinline__ void ldmx4(uint32_t* r, uint32_t addr) {
    asm volatile("ldmatrix.sync.aligned.m8n8.x4.shared.b16 {%0,%1,%2,%3}, [%4];"
                 : "=r"(r[0]), "=r"(r[1]), "=r"(r[2]), "=r"(r[3]) : "r"(addr));
}
__device__ __forceinline__ void ldmx4t(uint32_t* r, uint32_t addr) {
    asm volatile("ldmatrix.sync.aligned.m8n8.x4.trans.shared.b16 {%0,%1,%2,%3}, [%4];"
                 : "=r"(r[0]), "=r"(r[1]), "=r"(r[2]), "=r"(r[3]) : "r"(addr));
}
__device__ __forceinline__ void mma_f16(float* c, const uint32_t* a,
                                        uint32_t b0, uint32_t b1) {
    asm volatile(
        "mma.sync.aligned.m16n8k16.row.col.f32.f16.f16.f32 "
        "{%0,%1,%2,%3}, {%4,%5,%6,%7}, {%8,%9}, {%0,%1,%2,%3};"
        : "+f"(c[0]), "+f"(c[1]), "+f"(c[2]), "+f"(c[3])
        : "r"(a[0]), "r"(a[1]), "r"(a[2]), "r"(a[3]), "r"(b0), "r"(b1));
}
__device__ __forceinline__ uint32_t packh2(float a, float b) {
    __half2 h = __floats2half2_rn(a, b);
    return *(uint32_t*)&h;
}

// =====================================================================
// conv_main: input fp16 conversions + Wq/Wk/Wv transposes (proj deps)
// =====================================================================
#define N4SEG (MROWS * DMODEL / 4)     // 2M float4 per tensor
#define CONV_BLOCKS (3 * N4SEG / 256)  // 24576
#define CM_BLOCKS (CONV_BLOCKS + 3072)

__global__ __launch_bounds__(256) void conv_main(
    const float* __restrict__ x0, const float* __restrict__ x1,
    const float* __restrict__ x2,
    __half* __restrict__ o0c, __half* __restrict__ o1c, __half* __restrict__ o2c,
    const float* __restrict__ Wq, const float* __restrict__ Wk,
    const float* __restrict__ Wv,
    __half* __restrict__ oQ, __half* __restrict__ oK, __half* __restrict__ oV)
{
    __shared__ float t[32][33];
    if (blockIdx.x < CONV_BLOCKS) {
        int i = blockIdx.x * 256 + threadIdx.x;
        int seg = i / N4SEG;
        int j   = i - seg * N4SEG;
        const float* x = (seg == 0) ? x0 : (seg == 1) ? x1 : x2;
        __half* o      = (seg == 0) ? o0c : (seg == 1) ? o1c : o2c;
        float4 v = ((const float4*)x)[j];
        __half2* op = (__half2*)(o + (size_t)j * 4);
        op[0] = __floats2half2_rn(v.x, v.y);
        op[1] = __floats2half2_rn(v.z, v.w);
        return;
    }
    const int bid = blockIdx.x - CONV_BLOCKS;    // 0..3071
    const int l = bid & 1023;
    const int w = bid >> 10;
    const float* W   = (w == 0) ? Wq : (w == 1) ? Wk : Wv;
    __half* out      = (w == 0) ? oQ : (w == 1) ? oK : oV;
    const int bx = l & 31, by = l >> 5;
    const int k0 = by * 32, n0 = bx * 32;
    int tx = threadIdx.x & 31, ty = threadIdx.x >> 5;
    #pragma unroll
    for (int i = ty; i < 32; i += 8)
        t[i][tx] = W[(size_t)(k0 + i) * DMODEL + n0 + tx];
    __syncthreads();
    #pragma unroll
    for (int i = ty; i < 32; i += 8)
        out[(size_t)(n0 + i) * DMODEL + k0 + tx] = __float2half(t[tx][i]);
}

// =====================================================================
// wt_ff: W1/W2 transposes (needed only by FF1/FF2) — runs on stream 2
// blocks [0,4096): W1 (K=1024,N=4096,gx=128); [4096,8192): W2 (K=4096,N=1024,gx=32)
// =====================================================================
#define WTFF_BLOCKS 8192
__global__ __launch_bounds__(256) void wt_ff(
    const float* __restrict__ W1, const float* __restrict__ W2,
    __half* __restrict__ o1, __half* __restrict__ o2)
{
    __shared__ float t[32][33];
    const int bid = blockIdx.x;
    const float* W; __half* out; int K, N, l, gx;
    if (bid < 4096) { l = bid;        gx = 128; K = DMODEL; N = DFF;  W = W1; out = o1; }
    else            { l = bid - 4096; gx = 32;  K = DFF; N = DMODEL;  W = W2; out = o2; }
    const int bx = l % gx, by = l / gx;
    const int k0 = by * 32, n0 = bx * 32;
    int tx = threadIdx.x & 31, ty = threadIdx.x >> 5;
    #pragma unroll
    for (int i = ty; i < 32; i += 8)
        t[i][tx] = W[(size_t)(k0 + i) * N + n0 + tx];
    __syncthreads();
    #pragma unroll
    for (int i = ty; i < 32; i += 8)
        out[(size_t)(n0 + i) * K + k0 + tx] = __float2half(t[tx][i]);
}

// =====================================================================
// fp16 GEMM core: BK=64, NSTAGE=3, depth-1 prefetch, ONE barrier/chunk
// (BM=128, occ-2) — R12 configuration
// =====================================================================
#define BM 128
#define BN 128
#define BK 64
#define ROWB 144
#define OPB  (128 * ROWB)
#define NSTAGE 3
#define STAGE16 (2 * OPB)
#define GEMM16_SMEM (NSTAGE * STAGE16)

__device__ __forceinline__ void prefetch16(
    uint32_t sbase, int stage, int c,
    const __half* A, const __half* B, int m0, int n0, int K, int tid)
{
    const int k0 = c * BK;
    const uint32_t sb = sbase + stage * STAGE16;
    #pragma unroll
    for (int t = 0; t < 4; t++) {
        int seg = tid + 256 * t;
        int row = seg >> 3;
        int sc  = seg & 7;
        uint32_t soff = row * ROWB + sc * 16;
        cp_async16(sb + soff,       A + (size_t)(m0 + row) * K + k0 + sc * 8);
        cp_async16(sb + OPB + soff, B + (size_t)(n0 + row) * K + k0 + sc * 8);
    }
}

__device__ __forceinline__ void gemm_core(
    uint32_t sbase, const __half* A, const __half* B,
    int m0, int n0, int K, int tid, int wid, int lane,
    float acc[2][8][4])
{
    const int wm = wid >> 1;
    const int wn = wid & 1;
    const int NC = K / BK;

    prefetch16(sbase, 0, 0, A, B, m0, n0, K, tid); CP_COMMIT();

    const uint32_t lrow = (lane & 15);
    const uint32_t lcol = (lane >> 4) * 16;

    int stg_i = 0, stg_n = 1;
    for (int c = 0; c < NC; c++) {
        if (c + 1 < NC) {
            prefetch16(sbase, stg_n, c + 1, A, B, m0, n0, K, tid);
            CP_COMMIT();
            asm volatile("cp.async.wait_group 1;" ::: "memory");
        } else {
            asm volatile("cp.async.wait_group 0;" ::: "memory");
        }
        __syncthreads();

        const uint32_t stg = sbase + stg_i * STAGE16;
        const uint32_t aBase = stg + (wm * 32) * ROWB + lrow * ROWB + lcol;
        const uint32_t bBase = stg + OPB + (wn * 64) * ROWB + lrow * ROWB + lcol;

        #pragma unroll
        for (int kk = 0; kk < 4; kk++) {
            const uint32_t kb = kk * 32;
            uint32_t ah[2][4];
            #pragma unroll
            for (int mt = 0; mt < 2; mt++)
                ldmx4(ah[mt], aBase + mt * 16 * ROWB + kb);
            #pragma unroll
            for (int p = 0; p < 4; p++) {
                uint32_t bh[4];
                ldmx4(bh, bBase + p * 16 * ROWB + kb);
                #pragma unroll
                for (int mt = 0; mt < 2; mt++) {
                    mma_f16(acc[mt][2*p],   ah[mt], bh[0], bh[2]);
                    mma_f16(acc[mt][2*p+1], ah[mt], bh[1], bh[3]);
                }
            }
        }
        stg_i = stg_n;
        stg_n = (stg_n == 2) ? 0 : stg_n + 1;
    }
}

// ---- z-batched QKV projection: out fp16 head-permuted [B,H,S,hd] ----
__global__ __launch_bounds__(256, 2) void gemm_proj(
    const __half* __restrict__ A0, const __half* __restrict__ A1,
    const __half* __restrict__ A2,
    const float* __restrict__ b0c, const float* __restrict__ b1c,
    const float* __restrict__ b2c,
    __half* __restrict__ o0, __half* __restrict__ o1, __half* __restrict__ o2)
{
    extern __shared__ char smem[];
    const uint32_t sbase = smem_u32(smem);
    const int tid = threadIdx.x;
    const int wid = tid >> 5, lane = tid & 31;
    const int z = blockIdx.z;
    const int m0 = blockIdx.y * BM, n0 = blockIdx.x * BN;

    const __half* A  = (z == 0) ? A0 : (z == 1) ? A1 : A2;
    const float* bias = (z == 0) ? b0c : (z == 1) ? b1c : b2c;
    __half* Ch       = (z == 0) ? o0 : (z == 1) ? o1 : o2;
    const float scale = (z == 0) ? QKSCALE : 1.0f;

    float acc[2][8][4];
    #pragma unroll
    for (int i = 0; i < 2; i++)
        #pragma unroll
        for (int j = 0; j < 8; j++)
            #pragma unroll
            for (int x = 0; x < 4; x++) acc[i][j][x] = 0.f;

    const __half* B = (z == 0) ? g_Wq16 : (z == 1) ? g_Wk16 : g_Wv16;
    gemm_core(sbase, A, B, m0, n0, DMODEL, tid, wid, lane, acc);

    const int wm = wid >> 1, wn = wid & 1;
    const int rbase = m0 + wm * 32 + (lane >> 2);
    const int cbase = n0 + wn * 64 + (lane & 3) * 2;
    #pragma unroll
    for (int mt = 0; mt < 2; mt++) {
        #pragma unroll
        for (int nt = 0; nt < 8; nt++) {
            const int col = cbase + nt * 8;
            const float bz0 = bias[col], bz1 = bias[col + 1];
            #pragma unroll
            for (int h = 0; h < 2; h++) {
                const int row = rbase + mt * 16 + h * 8;
                float v0 = (acc[mt][nt][2*h]   + bz0) * scale;
                float v1 = (acc[mt][nt][2*h+1] + bz1) * scale;
                const int b = row >> 11, s = row & (SEQ - 1);
                const int hh = col >> 7, d = col & (HD - 1);
                *(__half2*)(Ch + (((size_t)b * NHEAD + hh) * SEQ + s) * HD + d)
                    = __floats2half2_rn(v0, v1);
            }
        }
    }
}

// ---- generic FF GEMM: mode 0 f32 out, mode 1 ReLU + fp16 out ----
__global__ __launch_bounds__(256, 2) void gemm_f16(
    const __half* __restrict__ A, const __half* __restrict__ B,
    const float* __restrict__ bias, float* __restrict__ Cf,
    __half* __restrict__ Ch, int M, int N, int K, int mode)
{
    extern __shared__ char smem[];
    const uint32_t sbase = smem_u32(smem);
    const int tid = threadIdx.x;
    const int wid = tid >> 5, lane = tid & 31;
    const int m0 = blockIdx.y * BM, n0 = blockIdx.x * BN;

    float acc[2][8][4];
    #pragma unroll
    for (int i = 0; i < 2; i++)
        #pragma unroll
        for (int j = 0; j < 8; j++)
            #pragma unroll
            for (int x = 0; x < 4; x++) acc[i][j][x] = 0.f;

    gemm_core(sbase, A, B, m0, n0, K, tid, wid, lane, acc);

    const int wm = wid >> 1, wn = wid & 1;
    const int rbase = m0 + wm * 32 + (lane >> 2);
    const int cbase = n0 + wn * 64 + (lane & 3) * 2;
    #pragma unroll
    for (int mt = 0; mt < 2; mt++) {
        #pragma unroll
        for (int nt = 0; nt < 8; nt++) {
            const int col = cbase + nt * 8;
            const float bz0 = bias[col], bz1 = bias[col + 1];
            #pragma unroll
            for (int h = 0; h < 2; h++) {
                const int row = rbase + mt * 16 + h * 8;
                float v0 = acc[mt][nt][2*h]   + bz0;
                float v1 = acc[mt][nt][2*h+1] + bz1;
                if (mode == 0) {
                    float* dst = Cf + (size_t)row * N + col;
                    dst[0] = v0; dst[1] = v1;
                } else {
                    v0 = fmaxf(v0, 0.f); v1 = fmaxf(v1, 0.f);
                    *(__half2*)(Ch + (size_t)row * N + col) = __floats2half2_rn(v0, v1);
                }
            }
        }
    }
}

// =====================================================================
// fp16 flash attention: R12 configuration — 128 thr / 4 warps / 64-q
// tiles, occ-2, swizzled tiles, NS=3 ring, ONE barrier per key-tile.
// =====================================================================
#define ATHREADS 128
#define AQ 64
#define KTILE_B (64 * 256)             // 16384
#define STAGE_SZ (2 * KTILE_B)         // 32768
#define ANSTAGE 3
#define SKBASE KTILE_B                 // Q tile first: 16384
#define ATT_SMEM (SKBASE + ANSTAGE * STAGE_SZ)   // 114688

__device__ __forceinline__ void attn_prefetch(
    uint32_t sb, int stage, int kt,
    const __half* Kgb, const __half* Vgb, int tid)
{
    #pragma unroll
    for (int t = 0; t < 16; t++) {
        int idx = tid + t * ATHREADS;     // 0..2047
        int tensor = idx >> 10;           // 0: K, 1: V
        int row = (idx >> 4) & 63;
        int c   = idx & 15;
        uint32_t rel = row * 256 + (((uint32_t)c ^ (row & 7)) << 4);
        uint32_t dst = sb + SKBASE + stage * STAGE_SZ + tensor * KTILE_B + rel;
        const __half* src = (tensor ? Vgb : Kgb) + (size_t)(kt * 64 + row) * HD + c * 8;
        cp_async16(dst, src);
    }
}

__global__ __launch_bounds__(ATHREADS, 2) void attn_mma(
    const __half* __restrict__ Qg, const __half* __restrict__ Kg,
    const __half* __restrict__ Vg, float* __restrict__ mh)
{
    extern __shared__ char smem[];
    const uint32_t sb = smem_u32(smem);
    const int tid = threadIdx.x;
    const int wid = tid >> 5, lane = tid & 31;
    const int qb = blockIdx.x;
    const int bh = blockIdx.y;
    const int b = bh >> 3, h = bh & 7;

    const __half* Qgb = Qg + ((size_t)bh * SEQ + qb * AQ) * HD;
    #pragma unroll
    for (int t = 0; t < 8; t++) {
        int idx = tid + t * ATHREADS;
        int row = idx >> 4, c = idx & 15;
        uint32_t rel = row * 256 + (((uint32_t)c ^ (row & 7)) << 4);
        cp_async16(sb + rel, Qgb + (size_t)row * HD + c * 8);
    }
    CP_COMMIT();
    const __half* Kgb = Kg + (size_t)bh * SEQ * HD;
    const __half* Vgb = Vg + (size_t)bh * SEQ * HD;
    attn_prefetch(sb, 0, 0, Kgb, Vgb, tid);
    CP_COMMIT();

    asm volatile("cp.async.wait_group 0;" ::: "memory");
    __syncthreads();

    const uint32_t lrow = lane & 15;
    const uint32_t hi16 = (lane >> 4) * 16;
    const uint32_t lanexor = (lrow & 7) << 4;

    uint32_t qf[8][4];
    {
        const uint32_t qrow = sb + (wid * 16 + lrow) * 256;
        #pragma unroll
        for (int ks = 0; ks < 8; ks++)
            ldmx4(qf[ks], qrow + (((uint32_t)(ks * 32) + hi16) ^ lanexor));
    }

    float oacc[16][4];
    #pragma unroll
    for (int i = 0; i < 16; i++)
        #pragma unroll
        for (int j = 0; j < 4; j++) oacc[i][j] = 0.f;
    float m0 = -1e30f, m1 = -1e30f, l0 = 0.f, l1 = 0.f;

    int stg_i = 0, stg_n = 1;
    for (int kt = 0; kt < 32; kt++) {
        if (kt + 1 < 32) {
            attn_prefetch(sb, stg_n, kt + 1, Kgb, Vgb, tid);
            CP_COMMIT();
            asm volatile("cp.async.wait_group 1;" ::: "memory");
        } else {
            asm volatile("cp.async.wait_group 0;" ::: "memory");
        }
        __syncthreads();

        const uint32_t kbase = sb + SKBASE + stg_i * STAGE_SZ;
        const uint32_t vbase = kbase + KTILE_B;

        float sacc[8][4];
        #pragma unroll
        for (int i = 0; i < 8; i++)
            #pragma unroll
            for (int j = 0; j < 4; j++) sacc[i][j] = 0.f;

        #pragma unroll
        for (int ks = 0; ks < 8; ks++) {
            const uint32_t colb = ((uint32_t)(ks * 32) + hi16) ^ lanexor;
            #pragma unroll
            for (int p = 0; p < 4; p++) {
                uint32_t kf[4];
                ldmx4(kf, kbase + (p * 16 + lrow) * 256 + colb);
                mma_f16(sacc[2*p],   qf[ks], kf[0], kf[2]);
                mma_f16(sacc[2*p+1], qf[ks], kf[1], kf[3]);
            }
        }

        float mx0 = -1e30f, mx1 = -1e30f;
        #pragma unroll
        for (int n = 0; n < 8; n++) {
            mx0 = fmaxf(mx0, fmaxf(sacc[n][0], sacc[n][1]));
            mx1 = fmaxf(mx1, fmaxf(sacc[n][2], sacc[n][3]));
        }
        mx0 = fmaxf(mx0, __shfl_xor_sync(0xffffffffu, mx0, 1));
        mx0 = fmaxf(mx0, __shfl_xor_sync(0xffffffffu, mx0, 2));
        mx1 = fmaxf(mx1, __shfl_xor_sync(0xffffffffu, mx1, 1));
        mx1 = fmaxf(mx1, __shfl_xor_sync(0xffffffffu, mx1, 2));
        const float mn0 = fmaxf(m0, mx0), mn1 = fmaxf(m1, mx1);
        const float a0 = __expf(m0 - mn0), a1 = __expf(m1 - mn1);
        m0 = mn0; m1 = mn1;
        float sum0 = 0.f, sum1 = 0.f;
        #pragma unroll
        for (int n = 0; n < 8; n++) {
            sacc[n][0] = __expf(sacc[n][0] - mn0);
            sacc[n][1] = __expf(sacc[n][1] - mn0);
            sacc[n][2] = __expf(sacc[n][2] - mn1);
            sacc[n][3] = __expf(sacc[n][3] - mn1);
            sum0 += sacc[n][0] + sacc[n][1];
            sum1 += sacc[n][2] + sacc[n][3];
        }
        sum0 += __shfl_xor_sync(0xffffffffu, sum0, 1);
        sum0 += __shfl_xor_sync(0xffffffffu, sum0, 2);
        sum1 += __shfl_xor_sync(0xffffffffu, sum1, 1);
        sum1 += __shfl_xor_sync(0xffffffffu, sum1, 2);
        l0 = l0 * a0 + sum0; l1 = l1 * a1 + sum1;
        #pragma unroll
        for (int i = 0; i < 16; i++) {
            oacc[i][0] *= a0; oacc[i][1] *= a0;
            oacc[i][2] *= a1; oacc[i][3] *= a1;
        }

        uint32_t ph[4][4];
        #pragma unroll
        for (int t = 0; t < 4; t++) {
            ph[t][0] = packh2(sacc[2*t][0],   sacc[2*t][1]);
            ph[t][1] = packh2(sacc[2*t][2],   sacc[2*t][3]);
            ph[t][2] = packh2(sacc[2*t+1][0], sacc[2*t+1][1]);
            ph[t][3] = packh2(sacc[2*t+1][2], sacc[2*t+1][3]);
        }

        #pragma unroll
        for (int t = 0; t < 4; t++) {
            const uint32_t vrow = vbase + (t * 16 + lrow) * 256;
            #pragma unroll
            for (int g = 0; g < 8; g++) {
                uint32_t vf[4];
                ldmx4t(vf, vrow + (((uint32_t)(g * 32) + hi16) ^ lanexor));
                mma_f16(oacc[2*g],   ph[t], vf[0], vf[1]);
                mma_f16(oacc[2*g+1], ph[t], vf[2], vf[3]);
            }
        }
        stg_i = stg_n;
        stg_n = (stg_n == 2) ? 0 : stg_n + 1;
    }

    const float inv0 = 1.f / l0, inv1 = 1.f / l1;
    const int row0 = qb * AQ + wid * 16 + (lane >> 2);
    float* base0 = mh + ((size_t)b * SEQ + row0) * DMODEL + h * HD + (lane & 3) * 2;
    float* base1 = base0 + 8 * DMODEL;
    #pragma unroll
    for (int nt = 0; nt < 16; nt++) {
        *(float2*)(base0 + nt * 8) = make_float2(oacc[nt][0] * inv0, oacc[nt][1] * inv0);
        *(float2*)(base1 + nt * 8) = make_float2(oacc[nt][2] * inv1, oacc[nt][3] * inv1);
    }
}

// =====================================================================
// LayerNorm (ddof=1, no eps) + residual — float4 vectorized (unchanged)
// =====================================================================
template<int F16OUT>
__global__ __launch_bounds__(256) void ln_res_k(
    const float* __restrict__ x, const float* __restrict__ res,
    float* __restrict__ out, __half* __restrict__ h16)
{
    const int D = DMODEL;
    const size_t row = blockIdx.x;
    const float* xr = x + row * D;
    const int tid = threadIdx.x;

    float4 v4 = ((const float4*)xr)[tid];
    float s  = v4.x + v4.y + v4.z + v4.w;
    float ss = fmaf(v4.x, v4.x, fmaf(v4.y, v4.y, fmaf(v4.z, v4.z, v4.w * v4.w)));

    #pragma unroll
    for (int off = 16; off > 0; off >>= 1) {
        s  += __shfl_xor_sync(0xffffffffu, s, off);
        ss += __shfl_xor_sync(0xffffffffu, ss, off);
    }
    __shared__ float sa[8], sbuf[8];
    int w = tid >> 5, l = tid & 31;
    if (l == 0) { sa[w] = s; sbuf[w] = ss; }
    __syncthreads();
    if (tid < 32) {
        s  = (l < 8) ? sa[l] : 0.f;
        ss = (l < 8) ? sbuf[l] : 0.f;
        #pragma unroll
        for (int off = 4; off > 0; off >>= 1) {
            s  += __shfl_xor_sync(0xffffffffu, s, off);
            ss += __shfl_xor_sync(0xffffffffu, ss, off);
        }
        if (l == 0) { sa[0] = s; sbuf[0] = ss; }
    }
    __syncthreads();
    s = sa[0]; ss = sbuf[0];

    float mean = s / (float)D;
    float var  = (ss - s * s / (float)D) / (float)(D - 1);
    float rstd = rsqrtf(var);

    float4 r4 = ((const float4*)(res + row * D))[tid];
    float4 o4;
    o4.x = r4.x + (v4.x - mean) * rstd;
    o4.y = r4.y + (v4.y - mean) * rstd;
    o4.z = r4.z + (v4.z - mean) * rstd;
    o4.w = r4.w + (v4.w - mean) * rstd;
    ((float4*)(out + row * D))[tid] = o4;
    if (F16OUT) {
        __half2* hp = (__half2*)(h16 + row * D + tid * 4);
        hp[0] = __floats2half2_rn(o4.x, o4.y);
        hp[1] = __floats2half2_rn(o4.z, o4.w);
    }
}

// =====================================================================
extern "C" void kernel_launch(void* const* d_in, const int* in_sizes, int n_in,
                              void* d_out, int out_size)
{
    const float* q  = (const float*)d_in[0];
    const float* k  = (const float*)d_in[1];
    const float* v  = (const float*)d_in[2];
    const float* Wq = (const float*)d_in[3];
    const float* bq = (const float*)d_in[4];
    const float* Wk = (const float*)d_in[5];
    const float* bk = (const float*)d_in[6];
    const float* Wv = (const float*)d_in[7];
    const float* bv = (const float*)d_in[8];
    const float* W1 = (const float*)d_in[9];
    const float* b1 = (const float*)d_in[10];
    const float* W2 = (const float*)d_in[11];
    const float* b2 = (const float*)d_in[12];

    float *tmp, *mh, *res1;
    __half *A16, *F16, *W1t, *W2t, *Wq16, *Wk16, *Wv16, *Qh, *Kh, *Vh;
    cudaGetSymbolAddress((void**)&tmp,  g_tmp);
    cudaGetSymbolAddress((void**)&mh,   g_mh);
    cudaGetSymbolAddress((void**)&res1, g_res1);
    cudaGetSymbolAddress((void**)&A16,  g_A16);
    cudaGetSymbolAddress((void**)&F16,  g_F16);
    cudaGetSymbolAddress((void**)&W1t,  g_W1t);
    cudaGetSymbolAddress((void**)&W2t,  g_W2t);
    cudaGetSymbolAddress((void**)&Wq16, g_Wq16);
    cudaGetSymbolAddress((void**)&Wk16, g_Wk16);
    cudaGetSymbolAddress((void**)&Wv16, g_Wv16);
    cudaGetSymbolAddress((void**)&Qh,   g_Qh);
    cudaGetSymbolAddress((void**)&Kh,   g_Kh);
    cudaGetSymbolAddress((void**)&Vh,   g_Vh);

    // q16 / k16 staged in first/second half of F16 (free until FF1 output)
    __half* v16 = A16;
    __half* q16 = F16;
    __half* k16 = F16 + (size_t)MROWS * DMODEL;

    cudaFuncSetAttribute(gemm_proj,
                         cudaFuncAttributeMaxDynamicSharedMemorySize, GEMM16_SMEM);
    cudaFuncSetAttribute(gemm_f16,
                         cudaFuncAttributeMaxDynamicSharedMemorySize, GEMM16_SMEM);
    cudaFuncSetAttribute(attn_mma,
                         cudaFuncAttributeMaxDynamicSharedMemorySize, ATT_SMEM);

    dim3 blk(256);
    dim3 gProj(DMODEL / BN, MROWS / BM, 3);   // (8, 64, 3)
    dim3 gFF1(DFF / BN, MROWS / BM);          // (32, 64)
    dim3 gFF2(DMODEL / BN, MROWS / BM);       // (8, 64)

    // fork: stream2 transposes W1/W2 while main does proj/attn/LN1
    cudaStream_t s2;
    cudaStreamCreateWithFlags(&s2, cudaStreamNonBlocking);
    cudaEvent_t evFork, evJoin;
    cudaEventCreateWithFlags(&evFork, cudaEventDisableTiming);
    cudaEventCreateWithFlags(&evJoin, cudaEventDisableTiming);

    // main: input conversions + Wq/Wk/Wv transposes (proj dependencies)
    conv_main<<<CM_BLOCKS, blk>>>(v, q, k, v16, q16, k16,
                                  Wq, Wk, Wv, Wq16, Wk16, Wv16);

    cudaEventRecord(evFork, 0);
    cudaStreamWaitEvent(s2, evFork, 0);
    wt_ff<<<WTFF_BLOCKS, blk, 0, s2>>>(W1, W2, W1t, W2t);
    cudaEventRecord(evJoin, s2);

    // Encoder calls multihead(v, q, k): Q-in=v, K-in=q, V-in=k
    gemm_proj<<<gProj, blk, GEMM16_SMEM>>>(v16, q16, k16, bq, bk, bv, Qh, Kh, Vh);

    attn_mma<<<dim3(SEQ / AQ, BATCH * NHEAD), dim3(ATHREADS), ATT_SMEM>>>(Qh, Kh, Vh, mh);

    // res1 = q + LN(mh); also emit fp16 for FF1 (A16 reused)
    ln_res_k<1><<<MROWS, blk>>>(mh, q, res1, A16);

    cudaStreamWaitEvent(0, evJoin, 0);   // join: W1t/W2t ready

    gemm_f16<<<gFF1, blk, GEMM16_SMEM>>>(A16, W1t, b1, nullptr, F16,
                                         MROWS, DFF, DMODEL, 1);
    gemm_f16<<<gFF2, blk, GEMM16_SMEM>>>(F16, W2t, b2, tmp, nullptr,
                                         MROWS, DMODEL, DFF, 0);

    ln_res_k<0><<<MROWS, blk>>>(tmp, res1, (float*)d_out, nullptr);

    cudaEventDestroy(evFork);
    cudaEventDestroy(evJoin);
    cudaStreamDestroy(s2);
}

// round 15
// speedup vs baseline: 1.0589x; 1.0166x over previous
#include <cuda_runtime.h>
#include <cuda_fp16.h>
#include <cstdint>

// Problem constants
#define BATCH 4
#define SEQ   2048
#define DMODEL 1024
#define NHEAD 8
#define HD    128
#define MROWS (BATCH*SEQ)        // 8192
#define DFF   4096
#define QKSCALE 0.08838834764831845f   // 1/sqrt(128)

// ---------------- scratch (no allocations allowed) ----------------
__device__ __half g_tmp16[(size_t)MROWS * DMODEL];   // ff2 out (fp16)
__device__ float g_mh[(size_t)MROWS * DMODEL];
__device__ float g_res1[(size_t)MROWS * DMODEL];
__device__ __half g_A16[(size_t)MROWS * DMODEL];     // v16, later LN1 fp16 out
__device__ __half g_F16[(size_t)MROWS * DFF];        // q16+k16 early, FF1 out later
__device__ __half g_W1t[(size_t)DFF * DMODEL];
__device__ __half g_W2t[(size_t)DFF * DMODEL];
__device__ __half g_Wq16[(size_t)DMODEL * DMODEL];
__device__ __half g_Wk16[(size_t)DMODEL * DMODEL];
__device__ __half g_Wv16[(size_t)DMODEL * DMODEL];
__device__ __half g_Qh[(size_t)MROWS * DMODEL];
__device__ __half g_Kh[(size_t)MROWS * DMODEL];
__device__ __half g_Vh[(size_t)MROWS * DMODEL];

// ======================= PTX helpers =======================
__device__ __forceinline__ uint32_t smem_u32(const void* p) {
    uint32_t a;
    asm("{ .reg .u64 t; cvta.to.shared.u64 t, %1; cvt.u32.u64 %0, t; }" : "=r"(a) : "l"(p));
    return a;
}
__device__ __forceinline__ void cp_async16(uint32_t saddr, const void* gaddr) {
    asm volatile("cp.async.cg.shared.global [%0], [%1], 16;" :: "r"(saddr), "l"(gaddr) : "memory");
}
#define CP_COMMIT() asm volatile("cp.async.commit_group;" ::: "memory")

__device__ __forceinline__ void ldmx4(uint32_t* r, uint32_t addr) {
    asm volatile("ldmatrix.sync.aligned.m8n8.x4.shared.b16 {%0,%1,%2,%3}, [%4];"
                 : "=r"(r[0]), "=r"(r[1]), "=r"(r[2]), "=r"(r[3]) : "r"(addr));
}
__device__ __forceinline__ void ldmx4t(uint32_t* r, uint32_t addr) {
    asm volatile("ldmatrix.sync.aligned.m8n8.x4.trans.shared.b16 {%0,%1,%2,%3}, [%4];"
                 : "=r"(r[0]), "=r"(r[1]), "=r"(r[2]), "=r"(r[3]) : "r"(addr));
}
__device__ __forceinline__ void mma_f16(float* c, const uint32_t* a,
                                        uint32_t b0, uint32_t b1) {
    asm volatile(
        "mma.sync.aligned.m16n8k16.row.col.f32.f16.f16.f32 "
        "{%0,%1,%2,%3}, {%4,%5,%6,%7}, {%8,%9}, {%0,%1,%2,%3};"
        : "+f"(c[0]), "+f"(c[1]), "+f"(c[2]), "+f"(c[3])
        : "r"(a[0]), "r"(a[1]), "r"(a[2]), "r"(a[3]), "r"(b0), "r"(b1));
}
__device__ __forceinline__ uint32_t packh2(float a, float b) {
    __half2 h = __floats2half2_rn(a, b);
    return *(uint32_t*)&h;
}

// =====================================================================
// fused conversions: inputs->fp16 AND all 5 weight transposes, ONE launch
// =====================================================================
#define N4SEG (MROWS * DMODEL / 4)     // 2M float4 per tensor
#define CONV_BLOCKS (3 * N4SEG / 256)  // 24576
#define WT_BLOCKS 11264
#define CW_BLOCKS (CONV_BLOCKS + WT_BLOCKS)

__global__ __launch_bounds__(256) void conv_wt_all(
    const float* __restrict__ x0, const float* __restrict__ x1,
    const float* __restrict__ x2,
    __half* __restrict__ o0c, __half* __restrict__ o1c, __half* __restrict__ o2c,
    const float* __restrict__ Wq, const float* __restrict__ Wk,
    const float* __restrict__ Wv, const float* __restrict__ W1,
    const float* __restrict__ W2,
    __half* __restrict__ oQ, __half* __restrict__ oK, __half* __restrict__ oV,
    __half* __restrict__ o1, __half* __restrict__ o2)
{
    __shared__ float t[32][33];
    if (blockIdx.x < CONV_BLOCKS) {
        int i = blockIdx.x * 256 + threadIdx.x;
        int seg = i / N4SEG;
        int j   = i - seg * N4SEG;
        const float* x = (seg == 0) ? x0 : (seg == 1) ? x1 : x2;
        __half* o      = (seg == 0) ? o0c : (seg == 1) ? o1c : o2c;
        float4 v = ((const float4*)x)[j];
        __half2* op = (__half2*)(o + (size_t)j * 4);
        op[0] = __floats2half2_rn(v.x, v.y);
        op[1] = __floats2half2_rn(v.z, v.w);
        return;
    }
    const int bid = blockIdx.x - CONV_BLOCKS;
    const float* W; __half* out; int K, N, l, gx;
    if (bid < 3072) {
        l = bid & 1023; gx = 32; K = DMODEL; N = DMODEL;
        int w = bid >> 10;
        W   = (w == 0) ? Wq : (w == 1) ? Wk : Wv;
        out = (w == 0) ? oQ : (w == 1) ? oK : oV;
    } else if (bid < 7168) {
        l = bid - 3072; gx = 128; K = DMODEL; N = DFF;  W = W1; out = o1;
    } else {
        l = bid - 7168; gx = 32;  K = DFF; N = DMODEL;  W = W2; out = o2;
    }
    const int bx = l % gx, by = l / gx;
    const int k0 = by * 32, n0 = bx * 32;
    int tx = threadIdx.x & 31, ty = threadIdx.x >> 5;
    #pragma unroll
    for (int i = ty; i < 32; i += 8)
        t[i][tx] = W[(size_t)(k0 + i) * N + n0 + tx];
    __syncthreads();
    #pragma unroll
    for (int i = ty; i < 32; i += 8)
        out[(size_t)(n0 + i) * K + k0 + tx] = __float2half(t[tx][i]);
}

// =====================================================================
// fp16 GEMM core: BK=64, NSTAGE=3, depth-1 prefetch, ONE barrier/chunk
// (BM=128, occ-2) — R12 configuration
// =====================================================================
#define BM 128
#define BN 128
#define BK 64
#define ROWB 144
#define OPB  (128 * ROWB)
#define NSTAGE 3
#define STAGE16 (2 * OPB)
#define GEMM16_SMEM (NSTAGE * STAGE16)

__device__ __forceinline__ void prefetch16(
    uint32_t sbase, int stage, int c,
    const __half* A, const __half* B, int m0, int n0, int K, int tid)
{
    const int k0 = c * BK;
    const uint32_t sb = sbase + stage * STAGE16;
    #pragma unroll
    for (int t = 0; t < 4; t++) {
        int seg = tid + 256 * t;
        int row = seg >> 3;
        int sc  = seg & 7;
        uint32_t soff = row * ROWB + sc * 16;
        cp_async16(sb + soff,       A + (size_t)(m0 + row) * K + k0 + sc * 8);
        cp_async16(sb + OPB + soff, B + (size_t)(n0 + row) * K + k0 + sc * 8);
    }
}

__device__ __forceinline__ void gemm_core(
    uint32_t sbase, const __half* A, const __half* B,
    int m0, int n0, int K, int tid, int wid, int lane,
    float acc[2][8][4])
{
    const int wm = wid >> 1;
    const int wn = wid & 1;
    const int NC = K / BK;

    prefetch16(sbase, 0, 0, A, B, m0, n0, K, tid); CP_COMMIT();

    const uint32_t lrow = (lane & 15);
    const uint32_t lcol = (lane >> 4) * 16;

    int stg_i = 0, stg_n = 1;
    for (int c = 0; c < NC; c++) {
        if (c + 1 < NC) {
            prefetch16(sbase, stg_n, c + 1, A, B, m0, n0, K, tid);
            CP_COMMIT();
            asm volatile("cp.async.wait_group 1;" ::: "memory");
        } else {
            asm volatile("cp.async.wait_group 0;" ::: "memory");
        }
        __syncthreads();

        const uint32_t stg = sbase + stg_i * STAGE16;
        const uint32_t aBase = stg + (wm * 32) * ROWB + lrow * ROWB + lcol;
        const uint32_t bBase = stg + OPB + (wn * 64) * ROWB + lrow * ROWB + lcol;

        #pragma unroll
        for (int kk = 0; kk < 4; kk++) {
            const uint32_t kb = kk * 32;
            uint32_t ah[2][4];
            #pragma unroll
            for (int mt = 0; mt < 2; mt++)
                ldmx4(ah[mt], aBase + mt * 16 * ROWB + kb);
            #pragma unroll
            for (int p = 0; p < 4; p++) {
                uint32_t bh[4];
                ldmx4(bh, bBase + p * 16 * ROWB + kb);
                #pragma unroll
                for (int mt = 0; mt < 2; mt++) {
                    mma_f16(acc[mt][2*p],   ah[mt], bh[0], bh[2]);
                    mma_f16(acc[mt][2*p+1], ah[mt], bh[1], bh[3]);
                }
            }
        }
        stg_i = stg_n;
        stg_n = (stg_n == 2) ? 0 : stg_n + 1;
    }
}

// ---- z-batched QKV projection: out fp16 head-permuted [B,H,S,hd] ----
__global__ __launch_bounds__(256, 2) void gemm_proj(
    const __half* __restrict__ A0, const __half* __restrict__ A1,
    const __half* __restrict__ A2,
    const float* __restrict__ b0c, const float* __restrict__ b1c,
    const float* __restrict__ b2c,
    __half* __restrict__ o0, __half* __restrict__ o1, __half* __restrict__ o2)
{
    extern __shared__ char smem[];
    const uint32_t sbase = smem_u32(smem);
    const int tid = threadIdx.x;
    const int wid = tid >> 5, lane = tid & 31;
    const int z = blockIdx.z;
    const int m0 = blockIdx.y * BM, n0 = blockIdx.x * BN;

    const __half* A  = (z == 0) ? A0 : (z == 1) ? A1 : A2;
    const float* bias = (z == 0) ? b0c : (z == 1) ? b1c : b2c;
    __half* Ch       = (z == 0) ? o0 : (z == 1) ? o1 : o2;
    const float scale = (z == 0) ? QKSCALE : 1.0f;

    float acc[2][8][4];
    #pragma unroll
    for (int i = 0; i < 2; i++)
        #pragma unroll
        for (int j = 0; j < 8; j++)
            #pragma unroll
            for (int x = 0; x < 4; x++) acc[i][j][x] = 0.f;

    const __half* B = (z == 0) ? g_Wq16 : (z == 1) ? g_Wk16 : g_Wv16;
    gemm_core(sbase, A, B, m0, n0, DMODEL, tid, wid, lane, acc);

    const int wm = wid >> 1, wn = wid & 1;
    const int rbase = m0 + wm * 32 + (lane >> 2);
    const int cbase = n0 + wn * 64 + (lane & 3) * 2;
    #pragma unroll
    for (int mt = 0; mt < 2; mt++) {
        #pragma unroll
        for (int nt = 0; nt < 8; nt++) {
            const int col = cbase + nt * 8;
            const float bz0 = bias[col], bz1 = bias[col + 1];
            #pragma unroll
            for (int h = 0; h < 2; h++) {
                const int row = rbase + mt * 16 + h * 8;
                float v0 = (acc[mt][nt][2*h]   + bz0) * scale;
                float v1 = (acc[mt][nt][2*h+1] + bz1) * scale;
                const int b = row >> 11, s = row & (SEQ - 1);
                const int hh = col >> 7, d = col & (HD - 1);
                *(__half2*)(Ch + (((size_t)b * NHEAD + hh) * SEQ + s) * HD + d)
                    = __floats2half2_rn(v0, v1);
            }
        }
    }
}

// ---- generic FF GEMM: fp16 out; mode 1 applies ReLU ----
__global__ __launch_bounds__(256, 2) void gemm_f16(
    const __half* __restrict__ A, const __half* __restrict__ B,
    const float* __restrict__ bias,
    __half* __restrict__ Ch, int M, int N, int K, int mode)
{
    extern __shared__ char smem[];
    const uint32_t sbase = smem_u32(smem);
    const int tid = threadIdx.x;
    const int wid = tid >> 5, lane = tid & 31;
    const int m0 = blockIdx.y * BM, n0 = blockIdx.x * BN;

    float acc[2][8][4];
    #pragma unroll
    for (int i = 0; i < 2; i++)
        #pragma unroll
        for (int j = 0; j < 8; j++)
            #pragma unroll
            for (int x = 0; x < 4; x++) acc[i][j][x] = 0.f;

    gemm_core(sbase, A, B, m0, n0, K, tid, wid, lane, acc);

    const int wm = wid >> 1, wn = wid & 1;
    const int rbase = m0 + wm * 32 + (lane >> 2);
    const int cbase = n0 + wn * 64 + (lane & 3) * 2;
    #pragma unroll
    for (int mt = 0; mt < 2; mt++) {
        #pragma unroll
        for (int nt = 0; nt < 8; nt++) {
            const int col = cbase + nt * 8;
            const float bz0 = bias[col], bz1 = bias[col + 1];
            #pragma unroll
            for (int h = 0; h < 2; h++) {
                const int row = rbase + mt * 16 + h * 8;
                float v0 = acc[mt][nt][2*h]   + bz0;
                float v1 = acc[mt][nt][2*h+1] + bz1;
                if (mode == 1) { v0 = fmaxf(v0, 0.f); v1 = fmaxf(v1, 0.f); }
                *(__half2*)(Ch + (size_t)row * N + col) = __floats2half2_rn(v0, v1);
            }
        }
    }
}

// =====================================================================
// fp16 flash attention: R12 configuration — 128 thr / 4 warps / 64-q
// tiles, occ-2, swizzled tiles, NS=3 ring, ONE barrier per key-tile.
// =====================================================================
#define ATHREADS 128
#define AQ 64
#define KTILE_B (64 * 256)             // 16384
#define STAGE_SZ (2 * KTILE_B)         // 32768
#define ANSTAGE 3
#define SKBASE KTILE_B                 // Q tile first: 16384
#define ATT_SMEM (SKBASE + ANSTAGE * STAGE_SZ)   // 114688

__device__ __forceinline__ void attn_prefetch(
    uint32_t sb, int stage, int kt,
    const __half* Kgb, const __half* Vgb, int tid)
{
    #pragma unroll
    for (int t = 0; t < 16; t++) {
        int idx = tid + t * ATHREADS;     // 0..2047
        int tensor = idx >> 10;           // 0: K, 1: V
        int row = (idx >> 4) & 63;
        int c   = idx & 15;
        uint32_t rel = row * 256 + (((uint32_t)c ^ (row & 7)) << 4);
        uint32_t dst = sb + SKBASE + stage * STAGE_SZ + tensor * KTILE_B + rel;
        const __half* src = (tensor ? Vgb : Kgb) + (size_t)(kt * 64 + row) * HD + c * 8;
        cp_async16(dst, src);
    }
}

__global__ __launch_bounds__(ATHREADS, 2) void attn_mma(
    const __half* __restrict__ Qg, const __half* __restrict__ Kg,
    const __half* __restrict__ Vg, float* __restrict__ mh)
{
    extern __shared__ char smem[];
    const uint32_t sb = smem_u32(smem);
    const int tid = threadIdx.x;
    const int wid = tid >> 5, lane = tid & 31;
    const int qb = blockIdx.x;
    const int bh = blockIdx.y;
    const int b = bh >> 3, h = bh & 7;

    const __half* Qgb = Qg + ((size_t)bh * SEQ + qb * AQ) * HD;
    #pragma unroll
    for (int t = 0; t < 8; t++) {
        int idx = tid + t * ATHREADS;
        int row = idx >> 4, c = idx & 15;
        uint32_t rel = row * 256 + (((uint32_t)c ^ (row & 7)) << 4);
        cp_async16(sb + rel, Qgb + (size_t)row * HD + c * 8);
    }
    CP_COMMIT();
    const __half* Kgb = Kg + (size_t)bh * SEQ * HD;
    const __half* Vgb = Vg + (size_t)bh * SEQ * HD;
    attn_prefetch(sb, 0, 0, Kgb, Vgb, tid);
    CP_COMMIT();

    asm volatile("cp.async.wait_group 0;" ::: "memory");
    __syncthreads();

    const uint32_t lrow = lane & 15;
    const uint32_t hi16 = (lane >> 4) * 16;
    const uint32_t lanexor = (lrow & 7) << 4;

    uint32_t qf[8][4];
    {
        const uint32_t qrow = sb + (wid * 16 + lrow) * 256;
        #pragma unroll
        for (int ks = 0; ks < 8; ks++)
            ldmx4(qf[ks], qrow + (((uint32_t)(ks * 32) + hi16) ^ lanexor));
    }

    float oacc[16][4];
    #pragma unroll
    for (int i = 0; i < 16; i++)
        #pragma unroll
        for (int j = 0; j < 4; j++) oacc[i][j] = 0.f;
    float m0 = -1e30f, m1 = -1e30f, l0 = 0.f, l1 = 0.f;

    int stg_i = 0, stg_n = 1;
    for (int kt = 0; kt < 32; kt++) {
        if (kt + 1 < 32) {
            attn_prefetch(sb, stg_n, kt + 1, Kgb, Vgb, tid);
            CP_COMMIT();
            asm volatile("cp.async.wait_group 1;" ::: "memory");
        } else {
            asm volatile("cp.async.wait_group 0;" ::: "memory");
        }
        __syncthreads();

        const uint32_t kbase = sb + SKBASE + stg_i * STAGE_SZ;
        const uint32_t vbase = kbase + KTILE_B;

        float sacc[8][4];
        #pragma unroll
        for (int i = 0; i < 8; i++)
            #pragma unroll
            for (int j = 0; j < 4; j++) sacc[i][j] = 0.f;

        #pragma unroll
        for (int ks = 0; ks < 8; ks++) {
            const uint32_t colb = ((uint32_t)(ks * 32) + hi16) ^ lanexor;
            #pragma unroll
            for (int p = 0; p < 4; p++) {
                uint32_t kf[4];
                ldmx4(kf, kbase + (p * 16 + lrow) * 256 + colb);
                mma_f16(sacc[2*p],   qf[ks], kf[0], kf[2]);
                mma_f16(sacc[2*p+1], qf[ks], kf[1], kf[3]);
            }
        }

        float mx0 = -1e30f, mx1 = -1e30f;
        #pragma unroll
        for (int n = 0; n < 8; n++) {
            mx0 = fmaxf(mx0, fmaxf(sacc[n][0], sacc[n][1]));
            mx1 = fmaxf(mx1, fmaxf(sacc[n][2], sacc[n][3]));
        }
        mx0 = fmaxf(mx0, __shfl_xor_sync(0xffffffffu, mx0, 1));
        mx0 = fmaxf(mx0, __shfl_xor_sync(0xffffffffu, mx0, 2));
        mx1 = fmaxf(mx1, __shfl_xor_sync(0xffffffffu, mx1, 1));
        mx1 = fmaxf(mx1, __shfl_xor_sync(0xffffffffu, mx1, 2));
        const float mn0 = fmaxf(m0, mx0), mn1 = fmaxf(m1, mx1);
        const float a0 = __expf(m0 - mn0), a1 = __expf(m1 - mn1);
        m0 = mn0; m1 = mn1;
        float sum0 = 0.f, sum1 = 0.f;
        #pragma unroll
        for (int n = 0; n < 8; n++) {
            sacc[n][0] = __expf(sacc[n][0] - mn0);
            sacc[n][1] = __expf(sacc[n][1] - mn0);
            sacc[n][2] = __expf(sacc[n][2] - mn1);
            sacc[n][3] = __expf(sacc[n][3] - mn1);
            sum0 += sacc[n][0] + sacc[n][1];
            sum1 += sacc[n][2] + sacc[n][3];
        }
        sum0 += __shfl_xor_sync(0xffffffffu, sum0, 1);
        sum0 += __shfl_xor_sync(0xffffffffu, sum0, 2);
        sum1 += __shfl_xor_sync(0xffffffffu, sum1, 1);
        sum1 += __shfl_xor_sync(0xffffffffu, sum1, 2);
        l0 = l0 * a0 + sum0; l1 = l1 * a1 + sum1;
        #pragma unroll
        for (int i = 0; i < 16; i++) {
            oacc[i][0] *= a0; oacc[i][1] *= a0;
            oacc[i][2] *= a1; oacc[i][3] *= a1;
        }

        uint32_t ph[4][4];
        #pragma unroll
        for (int t = 0; t < 4; t++) {
            ph[t][0] = packh2(sacc[2*t][0],   sacc[2*t][1]);
            ph[t][1] = packh2(sacc[2*t][2],   sacc[2*t][3]);
            ph[t][2] = packh2(sacc[2*t+1][0], sacc[2*t+1][1]);
            ph[t][3] = packh2(sacc[2*t+1][2], sacc[2*t+1][3]);
        }

        #pragma unroll
        for (int t = 0; t < 4; t++) {
            const uint32_t vrow = vbase + (t * 16 + lrow) * 256;
            #pragma unroll
            for (int g = 0; g < 8; g++) {
                uint32_t vf[4];
                ldmx4t(vf, vrow + (((uint32_t)(g * 32) + hi16) ^ lanexor));
                mma_f16(oacc[2*g],   ph[t], vf[0], vf[1]);
                mma_f16(oacc[2*g+1], ph[t], vf[2], vf[3]);
            }
        }
        stg_i = stg_n;
        stg_n = (stg_n == 2) ? 0 : stg_n + 1;
    }

    const float inv0 = 1.f / l0, inv1 = 1.f / l1;
    const int row0 = qb * AQ + wid * 16 + (lane >> 2);
    float* base0 = mh + ((size_t)b * SEQ + row0) * DMODEL + h * HD + (lane & 3) * 2;
    float* base1 = base0 + 8 * DMODEL;
    #pragma unroll
    for (int nt = 0; nt < 16; nt++) {
        *(float2*)(base0 + nt * 8) = make_float2(oacc[nt][0] * inv0, oacc[nt][1] * inv0);
        *(float2*)(base1 + nt * 8) = make_float2(oacc[nt][2] * inv1, oacc[nt][3] * inv1);
    }
}

// =====================================================================
// LayerNorm (ddof=1, no eps) + residual — float4 vectorized.
// XF16: x input is fp16.  F16OUT: also emit fp16 copy of output.
// =====================================================================
template<int XF16, int F16OUT>
__global__ __launch_bounds__(256) void ln_res_k(
    const void* __restrict__ xv, const float* __restrict__ res,
    float* __restrict__ out, __half* __restrict__ h16)
{
    const int D = DMODEL;
    const size_t row = blockIdx.x;
    const int tid = threadIdx.x;

    float4 v4;
    if (XF16) {
        const __half2* xr = (const __half2*)((const __half*)xv + row * D) + tid * 2;
        float2 a = __half22float2(xr[0]);
        float2 c = __half22float2(xr[1]);
        v4 = make_float4(a.x, a.y, c.x, c.y);
    } else {
        v4 = ((const float4*)((const float*)xv + row * D))[tid];
    }
    float s  = v4.x + v4.y + v4.z + v4.w;
    float ss = fmaf(v4.x, v4.x, fmaf(v4.y, v4.y, fmaf(v4.z, v4.z, v4.w * v4.w)));

    #pragma unroll
    for (int off = 16; off > 0; off >>= 1) {
        s  += __shfl_xor_sync(0xffffffffu, s, off);
        ss += __shfl_xor_sync(0xffffffffu, ss, off);
    }
    __shared__ float sa[8], sbuf[8];
    int w = tid >> 5, l = tid & 31;
    if (l == 0) { sa[w] = s; sbuf[w] = ss; }
    __syncthreads();
    if (tid < 32) {
        s  = (l < 8) ? sa[l] : 0.f;
        ss = (l < 8) ? sbuf[l] : 0.f;
        #pragma unroll
        for (int off = 4; off > 0; off >>= 1) {
            s  += __shfl_xor_sync(0xffffffffu, s, off);
            ss += __shfl_xor_sync(0xffffffffu, ss, off);
        }
        if (l == 0) { sa[0] = s; sbuf[0] = ss; }
    }
    __syncthreads();
    s = sa[0]; ss = sbuf[0];

    float mean = s / (float)D;
    float var  = (ss - s * s / (float)D) / (float)(D - 1);
    float rstd = rsqrtf(var);

    float4 r4 = ((const float4*)(res + row * D))[tid];
    float4 o4;
    o4.x = r4.x + (v4.x - mean) * rstd;
    o4.y = r4.y + (v4.y - mean) * rstd;
    o4.z = r4.z + (v4.z - mean) * rstd;
    o4.w = r4.w + (v4.w - mean) * rstd;
    ((float4*)(out + row * D))[tid] = o4;
    if (F16OUT) {
        __half2* hp = (__half2*)(h16 + row * D + tid * 4);
        hp[0] = __floats2half2_rn(o4.x, o4.y);
        hp[1] = __floats2half2_rn(o4.z, o4.w);
    }
}

// =====================================================================
extern "C" void kernel_launch(void* const* d_in, const int* in_sizes, int n_in,
                              void* d_out, int out_size)
{
    const float* q  = (const float*)d_in[0];
    const float* k  = (const float*)d_in[1];
    const float* v  = (const float*)d_in[2];
    const float* Wq = (const float*)d_in[3];
    const float* bq = (const float*)d_in[4];
    const float* Wk = (const float*)d_in[5];
    const float* bk = (const float*)d_in[6];
    const float* Wv = (const float*)d_in[7];
    const float* bv = (const float*)d_in[8];
    const float* W1 = (const float*)d_in[9];
    const float* b1 = (const float*)d_in[10];
    const float* W2 = (const float*)d_in[11];
    const float* b2 = (const float*)d_in[12];

    float *mh, *res1;
    __half *tmp16, *A16, *F16, *W1t, *W2t, *Wq16, *Wk16, *Wv16, *Qh, *Kh, *Vh;
    cudaGetSymbolAddress((void**)&tmp16, g_tmp16);
    cudaGetSymbolAddress((void**)&mh,   g_mh);
    cudaGetSymbolAddress((void**)&res1, g_res1);
    cudaGetSymbolAddress((void**)&A16,  g_A16);
    cudaGetSymbolAddress((void**)&F16,  g_F16);
    cudaGetSymbolAddress((void**)&W1t,  g_W1t);
    cudaGetSymbolAddress((void**)&W2t,  g_W2t);
    cudaGetSymbolAddress((void**)&Wq16, g_Wq16);
    cudaGetSymbolAddress((void**)&Wk16, g_Wk16);
    cudaGetSymbolAddress((void**)&Wv16, g_Wv16);
    cudaGetSymbolAddress((void**)&Qh,   g_Qh);
    cudaGetSymbolAddress((void**)&Kh,   g_Kh);
    cudaGetSymbolAddress((void**)&Vh,   g_Vh);

    // q16 / k16 staged in first/second half of F16 (free until FF1 output)
    __half* v16 = A16;
    __half* q16 = F16;
    __half* k16 = F16 + (size_t)MROWS * DMODEL;

    cudaFuncSetAttribute(gemm_proj,
                         cudaFuncAttributeMaxDynamicSharedMemorySize, GEMM16_SMEM);
    cudaFuncSetAttribute(gemm_f16,
                         cudaFuncAttributeMaxDynamicSharedMemorySize, GEMM16_SMEM);
    cudaFuncSetAttribute(attn_mma,
                         cudaFuncAttributeMaxDynamicSharedMemorySize, ATT_SMEM);

    dim3 blk(256);
    dim3 gProj(DMODEL / BN, MROWS / BM, 3);   // (8, 64, 3)
    dim3 gFF1(DFF / BN, MROWS / BM);          // (32, 64)
    dim3 gFF2(DMODEL / BN, MROWS / BM);       // (8, 64)

    // all format conversions, one launch
    conv_wt_all<<<CW_BLOCKS, blk>>>(v, q, k, v16, q16, k16,
                                    Wq, Wk, Wv, W1, W2,
                                    Wq16, Wk16, Wv16, W1t, W2t);

    // Encoder calls multihead(v, q, k): Q-in=v, K-in=q, V-in=k
    gemm_proj<<<gProj, blk, GEMM16_SMEM>>>(v16, q16, k16, bq, bk, bv, Qh, Kh, Vh);

    attn_mma<<<dim3(SEQ / AQ, BATCH * NHEAD), dim3(ATHREADS), ATT_SMEM>>>(Qh, Kh, Vh, mh);

    // res1 = q + LN(mh); also emit fp16 for FF1 (A16 reused)
    ln_res_k<0, 1><<<MROWS, blk>>>(mh, q, res1, A16);

    gemm_f16<<<gFF1, blk, GEMM16_SMEM>>>(A16, W1t, b1, F16,
                                         MROWS, DFF, DMODEL, 1);
    gemm_f16<<<gFF2, blk, GEMM16_SMEM>>>(F16, W2t, b2, tmp16,
                                         MROWS, DMODEL, DFF, 0);

    ln_res_k<1, 0><<<MROWS, blk>>>(tmp16, res1, (float*)d_out, nullptr);
}

// round 16
// speedup vs baseline: 1.0612x; 1.0021x over previous
#include <cuda_runtime.h>
#include <cuda_fp16.h>
#include <cstdint>

// Problem constants
#define BATCH 4
#define SEQ   2048
#define DMODEL 1024
#define NHEAD 8
#define HD    128
#define MROWS (BATCH*SEQ)        // 8192
#define DFF   4096
#define QKSCALE 0.08838834764831845f   // 1/sqrt(128)

// ---------------- scratch (no allocations allowed) ----------------
__device__ __half g_tmp16[(size_t)MROWS * DMODEL];   // ff2 out (fp16)
__device__ __half g_mh16[(size_t)MROWS * DMODEL];    // attention out (fp16)
__device__ float g_res1[(size_t)MROWS * DMODEL];
__device__ __half g_A16[(size_t)MROWS * DMODEL];     // v16, later LN1 fp16 out
__device__ __half g_F16[(size_t)MROWS * DFF];        // q16+k16 early, FF1 out later
__device__ __half g_W1t[(size_t)DFF * DMODEL];
__device__ __half g_W2t[(size_t)DFF * DMODEL];
__device__ __half g_Wq16[(size_t)DMODEL * DMODEL];
__device__ __half g_Wk16[(size_t)DMODEL * DMODEL];
__device__ __half g_Wv16[(size_t)DMODEL * DMODEL];
__device__ __half g_Qh[(size_t)MROWS * DMODEL];
__device__ __half g_Kh[(size_t)MROWS * DMODEL];
__device__ __half g_Vh[(size_t)MROWS * DMODEL];

// ======================= PTX helpers =======================
__device__ __forceinline__ uint32_t smem_u32(const void* p) {
    uint32_t a;
    asm("{ .reg .u64 t; cvta.to.shared.u64 t, %1; cvt.u32.u64 %0, t; }" : "=r"(a) : "l"(p));
    return a;
}
__device__ __forceinline__ void cp_async16(uint32_t saddr, const void* gaddr) {
    asm volatile("cp.async.cg.shared.global [%0], [%1], 16;" :: "r"(saddr), "l"(gaddr) : "memory");
}
#define CP_COMMIT() asm volatile("cp.async.commit_group;" ::: "memory")

__device__ __forceinline__ void ldmx4(uint32_t* r, uint32_t addr) {
    asm volatile("ldmatrix.sync.aligned.m8n8.x4.shared.b16 {%0,%1,%2,%3}, [%4];"
                 : "=r"(r[0]), "=r"(r[1]), "=r"(r[2]), "=r"(r[3]) : "r"(addr));
}
__device__ __forceinline__ void ldmx4t(uint32_t* r, uint32_t addr) {
    asm volatile("ldmatrix.sync.aligned.m8n8.x4.trans.shared.b16 {%0,%1,%2,%3}, [%4];"
                 : "=r"(r[0]), "=r"(r[1]), "=r"(r[2]), "=r"(r[3]) : "r"(addr));
}
__device__ __forceinline__ void mma_f16(float* c, const uint32_t* a,
                                        uint32_t b0, uint32_t b1) {
    asm volatile(
        "mma.sync.aligned.m16n8k16.row.col.f32.f16.f16.f32 "
        "{%0,%1,%2,%3}, {%4,%5,%6,%7}, {%8,%9}, {%0,%1,%2,%3};"
        : "+f"(c[0]), "+f"(c[1]), "+f"(c[2]), "+f"(c[3])
        : "r"(a[0]), "r"(a[1]), "r"(a[2]), "r"(a[3]), "r"(b0), "r"(b1));
}
__device__ __forceinline__ uint32_t packh2(float a, float b) {
    __half2 h = __floats2half2_rn(a, b);
    return *(uint32_t*)&h;
}

// =====================================================================
// fused conversions: inputs->fp16 AND all 5 weight transposes, ONE launch
// =====================================================================
#define N4SEG (MROWS * DMODEL / 4)     // 2M float4 per tensor
#define CONV_BLOCKS (3 * N4SEG / 256)  // 24576
#define WT_BLOCKS 11264
#define CW_BLOCKS (CONV_BLOCKS + WT_BLOCKS)

__global__ __launch_bounds__(256) void conv_wt_all(
    const float* __restrict__ x0, const float* __restrict__ x1,
    const float* __restrict__ x2,
    __half* __restrict__ o0c, __half* __restrict__ o1c, __half* __restrict__ o2c,
    const float* __restrict__ Wq, const float* __restrict__ Wk,
    const float* __restrict__ Wv, const float* __restrict__ W1,
    const float* __restrict__ W2,
    __half* __restrict__ oQ, __half* __restrict__ oK, __half* __restrict__ oV,
    __half* __restrict__ o1, __half* __restrict__ o2)
{
    __shared__ float t[32][33];
    if (blockIdx.x < CONV_BLOCKS) {
        int i = blockIdx.x * 256 + threadIdx.x;
        int seg = i / N4SEG;
        int j   = i - seg * N4SEG;
        const float* x = (seg == 0) ? x0 : (seg == 1) ? x1 : x2;
        __half* o      = (seg == 0) ? o0c : (seg == 1) ? o1c : o2c;
        float4 v = ((const float4*)x)[j];
        __half2* op = (__half2*)(o + (size_t)j * 4);
        op[0] = __floats2half2_rn(v.x, v.y);
        op[1] = __floats2half2_rn(v.z, v.w);
        return;
    }
    const int bid = blockIdx.x - CONV_BLOCKS;
    const float* W; __half* out; int K, N, l, gx;
    if (bid < 3072) {
        l = bid & 1023; gx = 32; K = DMODEL; N = DMODEL;
        int w = bid >> 10;
        W   = (w == 0) ? Wq : (w == 1) ? Wk : Wv;
        out = (w == 0) ? oQ : (w == 1) ? oK : oV;
    } else if (bid < 7168) {
        l = bid - 3072; gx = 128; K = DMODEL; N = DFF;  W = W1; out = o1;
    } else {
        l = bid - 7168; gx = 32;  K = DFF; N = DMODEL;  W = W2; out = o2;
    }
    const int bx = l % gx, by = l / gx;
    const int k0 = by * 32, n0 = bx * 32;
    int tx = threadIdx.x & 31, ty = threadIdx.x >> 5;
    #pragma unroll
    for (int i = ty; i < 32; i += 8)
        t[i][tx] = W[(size_t)(k0 + i) * N + n0 + tx];
    __syncthreads();
    #pragma unroll
    for (int i = ty; i < 32; i += 8)
        out[(size_t)(n0 + i) * K + k0 + tx] = __float2half(t[tx][i]);
}

// =====================================================================
// fp16 GEMM core: BK=64, NSTAGE=3, depth-1 prefetch, ONE barrier/chunk
// (BM=128, occ-2) — R12 configuration
// =====================================================================
#define BM 128
#define BN 128
#define BK 64
#define ROWB 144
#define OPB  (128 * ROWB)
#define NSTAGE 3
#define STAGE16 (2 * OPB)
#define GEMM16_SMEM (NSTAGE * STAGE16)

__device__ __forceinline__ void prefetch16(
    uint32_t sbase, int stage, int c,
    const __half* A, const __half* B, int m0, int n0, int K, int tid)
{
    const int k0 = c * BK;
    const uint32_t sb = sbase + stage * STAGE16;
    #pragma unroll
    for (int t = 0; t < 4; t++) {
        int seg = tid + 256 * t;
        int row = seg >> 3;
        int sc  = seg & 7;
        uint32_t soff = row * ROWB + sc * 16;
        cp_async16(sb + soff,       A + (size_t)(m0 + row) * K + k0 + sc * 8);
        cp_async16(sb + OPB + soff, B + (size_t)(n0 + row) * K + k0 + sc * 8);
    }
}

__device__ __forceinline__ void gemm_core(
    uint32_t sbase, const __half* A, const __half* B,
    int m0, int n0, int K, int tid, int wid, int lane,
    float acc[2][8][4])
{
    const int wm = wid >> 1;
    const int wn = wid & 1;
    const int NC = K / BK;

    prefetch16(sbase, 0, 0, A, B, m0, n0, K, tid); CP_COMMIT();

    const uint32_t lrow = (lane & 15);
    const uint32_t lcol = (lane >> 4) * 16;

    int stg_i = 0, stg_n = 1;
    for (int c = 0; c < NC; c++) {
        if (c + 1 < NC) {
            prefetch16(sbase, stg_n, c + 1, A, B, m0, n0, K, tid);
            CP_COMMIT();
            asm volatile("cp.async.wait_group 1;" ::: "memory");
        } else {
            asm volatile("cp.async.wait_group 0;" ::: "memory");
        }
        __syncthreads();

        const uint32_t stg = sbase + stg_i * STAGE16;
        const uint32_t aBase = stg + (wm * 32) * ROWB + lrow * ROWB + lcol;
        const uint32_t bBase = stg + OPB + (wn * 64) * ROWB + lrow * ROWB + lcol;

        #pragma unroll
        for (int kk = 0; kk < 4; kk++) {
            const uint32_t kb = kk * 32;
            uint32_t ah[2][4];
            #pragma unroll
            for (int mt = 0; mt < 2; mt++)
                ldmx4(ah[mt], aBase + mt * 16 * ROWB + kb);
            #pragma unroll
            for (int p = 0; p < 4; p++) {
                uint32_t bh[4];
                ldmx4(bh, bBase + p * 16 * ROWB + kb);
                #pragma unroll
                for (int mt = 0; mt < 2; mt++) {
                    mma_f16(acc[mt][2*p],   ah[mt], bh[0], bh[2]);
                    mma_f16(acc[mt][2*p+1], ah[mt], bh[1], bh[3]);
                }
            }
        }
        stg_i = stg_n;
        stg_n = (stg_n == 2) ? 0 : stg_n + 1;
    }
}

// ---- z-batched QKV projection: out fp16 head-permuted [B,H,S,hd] ----
__global__ __launch_bounds__(256, 2) void gemm_proj(
    const __half* __restrict__ A0, const __half* __restrict__ A1,
    const __half* __restrict__ A2,
    const float* __restrict__ b0c, const float* __restrict__ b1c,
    const float* __restrict__ b2c,
    __half* __restrict__ o0, __half* __restrict__ o1, __half* __restrict__ o2)
{
    extern __shared__ char smem[];
    const uint32_t sbase = smem_u32(smem);
    const int tid = threadIdx.x;
    const int wid = tid >> 5, lane = tid & 31;
    const int z = blockIdx.z;
    const int m0 = blockIdx.y * BM, n0 = blockIdx.x * BN;

    const __half* A  = (z == 0) ? A0 : (z == 1) ? A1 : A2;
    const float* bias = (z == 0) ? b0c : (z == 1) ? b1c : b2c;
    __half* Ch       = (z == 0) ? o0 : (z == 1) ? o1 : o2;
    const float scale = (z == 0) ? QKSCALE : 1.0f;

    float acc[2][8][4];
    #pragma unroll
    for (int i = 0; i < 2; i++)
        #pragma unroll
        for (int j = 0; j < 8; j++)
            #pragma unroll
            for (int x = 0; x < 4; x++) acc[i][j][x] = 0.f;

    const __half* B = (z == 0) ? g_Wq16 : (z == 1) ? g_Wk16 : g_Wv16;
    gemm_core(sbase, A, B, m0, n0, DMODEL, tid, wid, lane, acc);

    const int wm = wid >> 1, wn = wid & 1;
    const int rbase = m0 + wm * 32 + (lane >> 2);
    const int cbase = n0 + wn * 64 + (lane & 3) * 2;
    #pragma unroll
    for (int mt = 0; mt < 2; mt++) {
        #pragma unroll
        for (int nt = 0; nt < 8; nt++) {
            const int col = cbase + nt * 8;
            const float bz0 = bias[col], bz1 = bias[col + 1];
            #pragma unroll
            for (int h = 0; h < 2; h++) {
                const int row = rbase + mt * 16 + h * 8;
                float v0 = (acc[mt][nt][2*h]   + bz0) * scale;
                float v1 = (acc[mt][nt][2*h+1] + bz1) * scale;
                const int b = row >> 11, s = row & (SEQ - 1);
                const int hh = col >> 7, d = col & (HD - 1);
                *(__half2*)(Ch + (((size_t)b * NHEAD + hh) * SEQ + s) * HD + d)
                    = __floats2half2_rn(v0, v1);
            }
        }
    }
}

// ---- generic FF GEMM: fp16 out; mode 1 applies ReLU ----
__global__ __launch_bounds__(256, 2) void gemm_f16(
    const __half* __restrict__ A, const __half* __restrict__ B,
    const float* __restrict__ bias,
    __half* __restrict__ Ch, int M, int N, int K, int mode)
{
    extern __shared__ char smem[];
    const uint32_t sbase = smem_u32(smem);
    const int tid = threadIdx.x;
    const int wid = tid >> 5, lane = tid & 31;
    const int m0 = blockIdx.y * BM, n0 = blockIdx.x * BN;

    float acc[2][8][4];
    #pragma unroll
    for (int i = 0; i < 2; i++)
        #pragma unroll
        for (int j = 0; j < 8; j++)
            #pragma unroll
            for (int x = 0; x < 4; x++) acc[i][j][x] = 0.f;

    gemm_core(sbase, A, B, m0, n0, K, tid, wid, lane, acc);

    const int wm = wid >> 1, wn = wid & 1;
    const int rbase = m0 + wm * 32 + (lane >> 2);
    const int cbase = n0 + wn * 64 + (lane & 3) * 2;
    #pragma unroll
    for (int mt = 0; mt < 2; mt++) {
        #pragma unroll
        for (int nt = 0; nt < 8; nt++) {
            const int col = cbase + nt * 8;
            const float bz0 = bias[col], bz1 = bias[col + 1];
            #pragma unroll
            for (int h = 0; h < 2; h++) {
                const int row = rbase + mt * 16 + h * 8;
                float v0 = acc[mt][nt][2*h]   + bz0;
                float v1 = acc[mt][nt][2*h+1] + bz1;
                if (mode == 1) { v0 = fmaxf(v0, 0.f); v1 = fmaxf(v1, 0.f); }
                *(__half2*)(Ch + (size_t)row * N + col) = __floats2half2_rn(v0, v1);
            }
        }
    }
}

// =====================================================================
// fp16 flash attention: R12 configuration — 128 thr / 4 warps / 64-q
// tiles, occ-2, swizzled tiles, NS=3 ring, ONE barrier per key-tile.
// Output mh now fp16.
// =====================================================================
#define ATHREADS 128
#define AQ 64
#define KTILE_B (64 * 256)             // 16384
#define STAGE_SZ (2 * KTILE_B)         // 32768
#define ANSTAGE 3
#define SKBASE KTILE_B                 // Q tile first: 16384
#define ATT_SMEM (SKBASE + ANSTAGE * STAGE_SZ)   // 114688

__device__ __forceinline__ void attn_prefetch(
    uint32_t sb, int stage, int kt,
    const __half* Kgb, const __half* Vgb, int tid)
{
    #pragma unroll
    for (int t = 0; t < 16; t++) {
        int idx = tid + t * ATHREADS;     // 0..2047
        int tensor = idx >> 10;           // 0: K, 1: V
        int row = (idx >> 4) & 63;
        int c   = idx & 15;
        uint32_t rel = row * 256 + (((uint32_t)c ^ (row & 7)) << 4);
        uint32_t dst = sb + SKBASE + stage * STAGE_SZ + tensor * KTILE_B + rel;
        const __half* src = (tensor ? Vgb : Kgb) + (size_t)(kt * 64 + row) * HD + c * 8;
        cp_async16(dst, src);
    }
}

__global__ __launch_bounds__(ATHREADS, 2) void attn_mma(
    const __half* __restrict__ Qg, const __half* __restrict__ Kg,
    const __half* __restrict__ Vg, __half* __restrict__ mh)
{
    extern __shared__ char smem[];
    const uint32_t sb = smem_u32(smem);
    const int tid = threadIdx.x;
    const int wid = tid >> 5, lane = tid & 31;
    const int qb = blockIdx.x;
    const int bh = blockIdx.y;
    const int b = bh >> 3, h = bh & 7;

    const __half* Qgb = Qg + ((size_t)bh * SEQ + qb * AQ) * HD;
    #pragma unroll
    for (int t = 0; t < 8; t++) {
        int idx = tid + t * ATHREADS;
        int row = idx >> 4, c = idx & 15;
        uint32_t rel = row * 256 + (((uint32_t)c ^ (row & 7)) << 4);
        cp_async16(sb + rel, Qgb + (size_t)row * HD + c * 8);
    }
    CP_COMMIT();
    const __half* Kgb = Kg + (size_t)bh * SEQ * HD;
    const __half* Vgb = Vg + (size_t)bh * SEQ * HD;
    attn_prefetch(sb, 0, 0, Kgb, Vgb, tid);
    CP_COMMIT();

    asm volatile("cp.async.wait_group 0;" ::: "memory");
    __syncthreads();

    const uint32_t lrow = lane & 15;
    const uint32_t hi16 = (lane >> 4) * 16;
    const uint32_t lanexor = (lrow & 7) << 4;

    uint32_t qf[8][4];
    {
        const uint32_t qrow = sb + (wid * 16 + lrow) * 256;
        #pragma unroll
        for (int ks = 0; ks < 8; ks++)
            ldmx4(qf[ks], qrow + (((uint32_t)(ks * 32) + hi16) ^ lanexor));
    }

    float oacc[16][4];
    #pragma unroll
    for (int i = 0; i < 16; i++)
        #pragma unroll
        for (int j = 0; j < 4; j++) oacc[i][j] = 0.f;
    float m0 = -1e30f, m1 = -1e30f, l0 = 0.f, l1 = 0.f;

    int stg_i = 0, stg_n = 1;
    for (int kt = 0; kt < 32; kt++) {
        if (kt + 1 < 32) {
            attn_prefetch(sb, stg_n, kt + 1, Kgb, Vgb, tid);
            CP_COMMIT();
            asm volatile("cp.async.wait_group 1;" ::: "memory");
        } else {
            asm volatile("cp.async.wait_group 0;" ::: "memory");
        }
        __syncthreads();

        const uint32_t kbase = sb + SKBASE + stg_i * STAGE_SZ;
        const uint32_t vbase = kbase + KTILE_B;

        float sacc[8][4];
        #pragma unroll
        for (int i = 0; i < 8; i++)
            #pragma unroll
            for (int j = 0; j < 4; j++) sacc[i][j] = 0.f;

        #pragma unroll
        for (int ks = 0; ks < 8; ks++) {
            const uint32_t colb = ((uint32_t)(ks * 32) + hi16) ^ lanexor;
            #pragma unroll
            for (int p = 0; p < 4; p++) {
                uint32_t kf[4];
                ldmx4(kf, kbase + (p * 16 + lrow) * 256 + colb);
                mma_f16(sacc[2*p],   qf[ks], kf[0], kf[2]);
                mma_f16(sacc[2*p+1], qf[ks], kf[1], kf[3]);
            }
        }

        float mx0 = -1e30f, mx1 = -1e30f;
        #pragma unroll
        for (int n = 0; n < 8; n++) {
            mx0 = fmaxf(mx0, fmaxf(sacc[n][0], sacc[n][1]));
            mx1 = fmaxf(mx1, fmaxf(sacc[n][2], sacc[n][3]));
        }
        mx0 = fmaxf(mx0, __shfl_xor_sync(0xffffffffu, mx0, 1));
        mx0 = fmaxf(mx0, __shfl_xor_sync(0xffffffffu, mx0, 2));
        mx1 = fmaxf(mx1, __shfl_xor_sync(0xffffffffu, mx1, 1));
        mx1 = fmaxf(mx1, __shfl_xor_sync(0xffffffffu, mx1, 2));
        const float mn0 = fmaxf(m0, mx0), mn1 = fmaxf(m1, mx1);
        const float a0 = __expf(m0 - mn0), a1 = __expf(m1 - mn1);
        m0 = mn0; m1 = mn1;
        float sum0 = 0.f, sum1 = 0.f;
        #pragma unroll
        for (int n = 0; n < 8; n++) {
            sacc[n][0] = __expf(sacc[n][0] - mn0);
            sacc[n][1] = __expf(sacc[n][1] - mn0);
            sacc[n][2] = __expf(sacc[n][2] - mn1);
            sacc[n][3] = __expf(sacc[n][3] - mn1);
            sum0 += sacc[n][0] + sacc[n][1];
            sum1 += sacc[n][2] + sacc[n][3];
        }
        sum0 += __shfl_xor_sync(0xffffffffu, sum0, 1);
        sum0 += __shfl_xor_sync(0xffffffffu, sum0, 2);
        sum1 += __shfl_xor_sync(0xffffffffu, sum1, 1);
        sum1 += __shfl_xor_sync(0xffffffffu, sum1, 2);
        l0 = l0 * a0 + sum0; l1 = l1 * a1 + sum1;
        #pragma unroll
        for (int i = 0; i < 16; i++) {
            oacc[i][0] *= a0; oacc[i][1] *= a0;
            oacc[i][2] *= a1; oacc[i][3] *= a1;
        }

        uint32_t ph[4][4];
        #pragma unroll
        for (int t = 0; t < 4; t++) {
            ph[t][0] = packh2(sacc[2*t][0],   sacc[2*t][1]);
            ph[t][1] = packh2(sacc[2*t][2],   sacc[2*t][3]);
            ph[t][2] = packh2(sacc[2*t+1][0], sacc[2*t+1][1]);
            ph[t][3] = packh2(sacc[2*t+1][2], sacc[2*t+1][3]);
        }

        #pragma unroll
        for (int t = 0; t < 4; t++) {
            const uint32_t vrow = vbase + (t * 16 + lrow) * 256;
            #pragma unroll
            for (int g = 0; g < 8; g++) {
                uint32_t vf[4];
                ldmx4t(vf, vrow + (((uint32_t)(g * 32) + hi16) ^ lanexor));
                mma_f16(oacc[2*g],   ph[t], vf[0], vf[1]);
                mma_f16(oacc[2*g+1], ph[t], vf[2], vf[3]);
            }
        }
        stg_i = stg_n;
        stg_n = (stg_n == 2) ? 0 : stg_n + 1;
    }

    const float inv0 = 1.f / l0, inv1 = 1.f / l1;
    const int row0 = qb * AQ + wid * 16 + (lane >> 2);
    __half* base0 = mh + ((size_t)b * SEQ + row0) * DMODEL + h * HD + (lane & 3) * 2;
    __half* base1 = base0 + 8 * DMODEL;
    #pragma unroll
    for (int nt = 0; nt < 16; nt++) {
        *(__half2*)(base0 + nt * 8) =
            __floats2half2_rn(oacc[nt][0] * inv0, oacc[nt][1] * inv0);
        *(__half2*)(base1 + nt * 8) =
            __floats2half2_rn(oacc[nt][2] * inv1, oacc[nt][3] * inv1);
    }
}

// =====================================================================
// LayerNorm (ddof=1, no eps) + residual — float4 vectorized.
// XF16: x input is fp16.  F16OUT: also emit fp16 copy of output.
// =====================================================================
template<int XF16, int F16OUT>
__global__ __launch_bounds__(256) void ln_res_k(
    const void* __restrict__ xv, const float* __restrict__ res,
    float* __restrict__ out, __half* __restrict__ h16)
{
    const int D = DMODEL;
    const size_t row = blockIdx.x;
    const int tid = threadIdx.x;

    float4 v4;
    if (XF16) {
        const __half2* xr = (const __half2*)((const __half*)xv + row * D) + tid * 2;
        float2 a = __half22float2(xr[0]);
        float2 c = __half22float2(xr[1]);
        v4 = make_float4(a.x, a.y, c.x, c.y);
    } else {
        v4 = ((const float4*)((const float*)xv + row * D))[tid];
    }
    float s  = v4.x + v4.y + v4.z + v4.w;
    float ss = fmaf(v4.x, v4.x, fmaf(v4.y, v4.y, fmaf(v4.z, v4.z, v4.w * v4.w)));

    #pragma unroll
    for (int off = 16; off > 0; off >>= 1) {
        s  += __shfl_xor_sync(0xffffffffu, s, off);
        ss += __shfl_xor_sync(0xffffffffu, ss, off);
    }
    __shared__ float sa[8], sbuf[8];
    int w = tid >> 5, l = tid & 31;
    if (l == 0) { sa[w] = s; sbuf[w] = ss; }
    __syncthreads();
    if (tid < 32) {
        s  = (l < 8) ? sa[l] : 0.f;
        ss = (l < 8) ? sbuf[l] : 0.f;
        #pragma unroll
        for (int off = 4; off > 0; off >>= 1) {
            s  += __shfl_xor_sync(0xffffffffu, s, off);
            ss += __shfl_xor_sync(0xffffffffu, ss, off);
        }
        if (l == 0) { sa[0] = s; sbuf[0] = ss; }
    }
    __syncthreads();
    s = sa[0]; ss = sbuf[0];

    float mean = s / (float)D;
    float var  = (ss - s * s / (float)D) / (float)(D - 1);
    float rstd = rsqrtf(var);

    float4 r4 = ((const float4*)(res + row * D))[tid];
    float4 o4;
    o4.x = r4.x + (v4.x - mean) * rstd;
    o4.y = r4.y + (v4.y - mean) * rstd;
    o4.z = r4.z + (v4.z - mean) * rstd;
    o4.w = r4.w + (v4.w - mean) * rstd;
    ((float4*)(out + row * D))[tid] = o4;
    if (F16OUT) {
        __half2* hp = (__half2*)(h16 + row * D + tid * 4);
        hp[0] = __floats2half2_rn(o4.x, o4.y);
        hp[1] = __floats2half2_rn(o4.z, o4.w);
    }
}

// =====================================================================
extern "C" void kernel_launch(void* const* d_in, const int* in_sizes, int n_in,
                              void* d_out, int out_size)
{
    const float* q  = (const float*)d_in[0];
    const float* k  = (const float*)d_in[1];
    const float* v  = (const float*)d_in[2];
    const float* Wq = (const float*)d_in[3];
    const float* bq = (const float*)d_in[4];
    const float* Wk = (const float*)d_in[5];
    const float* bk = (const float*)d_in[6];
    const float* Wv = (const float*)d_in[7];
    const float* bv = (const float*)d_in[8];
    const float* W1 = (const float*)d_in[9];
    const float* b1 = (const float*)d_in[10];
    const float* W2 = (const float*)d_in[11];
    const float* b2 = (const float*)d_in[12];

    float *res1;
    __half *tmp16, *mh16, *A16, *F16, *W1t, *W2t, *Wq16, *Wk16, *Wv16, *Qh, *Kh, *Vh;
    cudaGetSymbolAddress((void**)&tmp16, g_tmp16);
    cudaGetSymbolAddress((void**)&mh16, g_mh16);
    cudaGetSymbolAddress((void**)&res1, g_res1);
    cudaGetSymbolAddress((void**)&A16,  g_A16);
    cudaGetSymbolAddress((void**)&F16,  g_F16);
    cudaGetSymbolAddress((void**)&W1t,  g_W1t);
    cudaGetSymbolAddress((void**)&W2t,  g_W2t);
    cudaGetSymbolAddress((void**)&Wq16, g_Wq16);
    cudaGetSymbolAddress((void**)&Wk16, g_Wk16);
    cudaGetSymbolAddress((void**)&Wv16, g_Wv16);
    cudaGetSymbolAddress((void**)&Qh,   g_Qh);
    cudaGetSymbolAddress((void**)&Kh,   g_Kh);
    cudaGetSymbolAddress((void**)&Vh,   g_Vh);

    // q16 / k16 staged in first/second half of F16 (free until FF1 output)
    __half* v16 = A16;
    __half* q16 = F16;
    __half* k16 = F16 + (size_t)MROWS * DMODEL;

    cudaFuncSetAttribute(gemm_proj,
                         cudaFuncAttributeMaxDynamicSharedMemorySize, GEMM16_SMEM);
    cudaFuncSetAttribute(gemm_f16,
                         cudaFuncAttributeMaxDynamicSharedMemorySize, GEMM16_SMEM);
    cudaFuncSetAttribute(attn_mma,
                         cudaFuncAttributeMaxDynamicSharedMemorySize, ATT_SMEM);

    dim3 blk(256);
    dim3 gProj(DMODEL / BN, MROWS / BM, 3);   // (8, 64, 3)
    dim3 gFF1(DFF / BN, MROWS / BM);          // (32, 64)
    dim3 gFF2(DMODEL / BN, MROWS / BM);       // (8, 64)

    // all format conversions, one launch
    conv_wt_all<<<CW_BLOCKS, blk>>>(v, q, k, v16, q16, k16,
                                    Wq, Wk, Wv, W1, W2,
                                    Wq16, Wk16, Wv16, W1t, W2t);

    // Encoder calls multihead(v, q, k): Q-in=v, K-in=q, V-in=k
    gemm_proj<<<gProj, blk, GEMM16_SMEM>>>(v16, q16, k16, bq, bk, bv, Qh, Kh, Vh);

    attn_mma<<<dim3(SEQ / AQ, BATCH * NHEAD), dim3(ATHREADS), ATT_SMEM>>>(Qh, Kh, Vh, mh16);

    // res1 = q + LN(mh); also emit fp16 for FF1 (A16 reused)
    ln_res_k<1, 1><<<MROWS, blk>>>(mh16, q, res1, A16);

    gemm_f16<<<gFF1, blk, GEMM16_SMEM>>>(A16, W1t, b1, F16,
                                         MROWS, DFF, DMODEL, 1);
    gemm_f16<<<gFF2, blk, GEMM16_SMEM>>>(F16, W2t, b2, tmp16,
                                         MROWS, DMODEL, DFF, 0);

    ln_res_k<1, 0><<<MROWS, blk>>>(tmp16, res1, (float*)d_out, nullptr);
}

// round 17
// speedup vs baseline: 1.0638x; 1.0025x over previous
#include <cuda_runtime.h>
#include <cuda_fp16.h>
#include <cstdint>

// Problem constants
#define BATCH 4
#define SEQ   2048
#define DMODEL 1024
#define NHEAD 8
#define HD    128
#define MROWS (BATCH*SEQ)        // 8192
#define DFF   4096
#define QKSCALE 0.08838834764831845f   // 1/sqrt(128)

// ---------------- scratch (no allocations allowed) ----------------
__device__ __half g_tmp16[(size_t)MROWS * DMODEL];   // ff2 out (fp16)
__device__ __half g_mh16[(size_t)MROWS * DMODEL];    // attention out (fp16)
__device__ __half g_res116[(size_t)MROWS * DMODEL];  // res1 (fp16) == FF1 input
__device__ __half g_A16[(size_t)MROWS * DMODEL];     // v16 staging
__device__ __half g_F16[(size_t)MROWS * DFF];        // q16+k16 early, FF1 out later
__device__ __half g_W1t[(size_t)DFF * DMODEL];
__device__ __half g_W2t[(size_t)DFF * DMODEL];
__device__ __half g_Wq16[(size_t)DMODEL * DMODEL];
__device__ __half g_Wk16[(size_t)DMODEL * DMODEL];
__device__ __half g_Wv16[(size_t)DMODEL * DMODEL];
__device__ __half g_Qh[(size_t)MROWS * DMODEL];
__device__ __half g_Kh[(size_t)MROWS * DMODEL];
__device__ __half g_Vh[(size_t)MROWS * DMODEL];

// ======================= PTX helpers =======================
__device__ __forceinline__ uint32_t smem_u32(const void* p) {
    uint32_t a;
    asm("{ .reg .u64 t; cvta.to.shared.u64 t, %1; cvt.u32.u64 %0, t; }" : "=r"(a) : "l"(p));
    return a;
}
__device__ __forceinline__ void cp_async16(uint32_t saddr, const void* gaddr) {
    asm volatile("cp.async.cg.shared.global [%0], [%1], 16;" :: "r"(saddr), "l"(gaddr) : "memory");
}
#define CP_COMMIT() asm volatile("cp.async.commit_group;" ::: "memory")

__device__ __forceinline__ void ldmx4(uint32_t* r, uint32_t addr) {
    asm volatile("ldmatrix.sync.aligned.m8n8.x4.shared.b16 {%0,%1,%2,%3}, [%4];"
                 : "=r"(r[0]), "=r"(r[1]), "=r"(r[2]), "=r"(r[3]) : "r"(addr));
}
__device__ __forceinline__ void ldmx4t(uint32_t* r, uint32_t addr) {
    asm volatile("ldmatrix.sync.aligned.m8n8.x4.trans.shared.b16 {%0,%1,%2,%3}, [%4];"
                 : "=r"(r[0]), "=r"(r[1]), "=r"(r[2]), "=r"(r[3]) : "r"(addr));
}
__device__ __forceinline__ void mma_f16(float* c, const uint32_t* a,
                                        uint32_t b0, uint32_t b1) {
    asm volatile(
        "mma.sync.aligned.m16n8k16.row.col.f32.f16.f16.f32 "
        "{%0,%1,%2,%3}, {%4,%5,%6,%7}, {%8,%9}, {%0,%1,%2,%3};"
        : "+f"(c[0]), "+f"(c[1]), "+f"(c[2]), "+f"(c[3])
        : "r"(a[0]), "r"(a[1]), "r"(a[2]), "r"(a[3]), "r"(b0), "r"(b1));
}
__device__ __forceinline__ uint32_t packh2(float a, float b) {
    __half2 h = __floats2half2_rn(a, b);
    return *(uint32_t*)&h;
}

// =====================================================================
// fused conversions: inputs->fp16 AND all 5 weight transposes, ONE launch
// =====================================================================
#define N4SEG (MROWS * DMODEL / 4)     // 2M float4 per tensor
#define CONV_BLOCKS (3 * N4SEG / 256)  // 24576
#define WT_BLOCKS 11264
#define CW_BLOCKS (CONV_BLOCKS + WT_BLOCKS)

__global__ __launch_bounds__(256) void conv_wt_all(
    const float* __restrict__ x0, const float* __restrict__ x1,
    const float* __restrict__ x2,
    __half* __restrict__ o0c, __half* __restrict__ o1c, __half* __restrict__ o2c,
    const float* __restrict__ Wq, const float* __restrict__ Wk,
    const float* __restrict__ Wv, const float* __restrict__ W1,
    const float* __restrict__ W2,
    __half* __restrict__ oQ, __half* __restrict__ oK, __half* __restrict__ oV,
    __half* __restrict__ o1, __half* __restrict__ o2)
{
    __shared__ float t[32][33];
    if (blockIdx.x < CONV_BLOCKS) {
        int i = blockIdx.x * 256 + threadIdx.x;
        int seg = i / N4SEG;
        int j   = i - seg * N4SEG;
        const float* x = (seg == 0) ? x0 : (seg == 1) ? x1 : x2;
        __half* o      = (seg == 0) ? o0c : (seg == 1) ? o1c : o2c;
        float4 v = ((const float4*)x)[j];
        __half2* op = (__half2*)(o + (size_t)j * 4);
        op[0] = __floats2half2_rn(v.x, v.y);
        op[1] = __floats2half2_rn(v.z, v.w);
        return;
    }
    const int bid = blockIdx.x - CONV_BLOCKS;
    const float* W; __half* out; int K, N, l, gx;
    if (bid < 3072) {
        l = bid & 1023; gx = 32; K = DMODEL; N = DMODEL;
        int w = bid >> 10;
        W   = (w == 0) ? Wq : (w == 1) ? Wk : Wv;
        out = (w == 0) ? oQ : (w == 1) ? oK : oV;
    } else if (bid < 7168) {
        l = bid - 3072; gx = 128; K = DMODEL; N = DFF;  W = W1; out = o1;
    } else {
        l = bid - 7168; gx = 32;  K = DFF; N = DMODEL;  W = W2; out = o2;
    }
    const int bx = l % gx, by = l / gx;
    const int k0 = by * 32, n0 = bx * 32;
    int tx = threadIdx.x & 31, ty = threadIdx.x >> 5;
    #pragma unroll
    for (int i = ty; i < 32; i += 8)
        t[i][tx] = W[(size_t)(k0 + i) * N + n0 + tx];
    __syncthreads();
    #pragma unroll
    for (int i = ty; i < 32; i += 8)
        out[(size_t)(n0 + i) * K + k0 + tx] = __float2half(t[tx][i]);
}

// =====================================================================
// fp16 GEMM core: BK=64, NSTAGE=3, depth-1 prefetch, ONE barrier/chunk
// (BM=128, occ-2)
// =====================================================================
#define BM 128
#define BN 128
#define BK 64
#define ROWB 144
#define OPB  (128 * ROWB)
#define NSTAGE 3
#define STAGE16 (2 * OPB)
#define GEMM16_SMEM (NSTAGE * STAGE16)

__device__ __forceinline__ void prefetch16(
    uint32_t sbase, int stage, int c,
    const __half* A, const __half* B, int m0, int n0, int K, int tid)
{
    const int k0 = c * BK;
    const uint32_t sb = sbase + stage * STAGE16;
    #pragma unroll
    for (int t = 0; t < 4; t++) {
        int seg = tid + 256 * t;
        int row = seg >> 3;
        int sc  = seg & 7;
        uint32_t soff = row * ROWB + sc * 16;
        cp_async16(sb + soff,       A + (size_t)(m0 + row) * K + k0 + sc * 8);
        cp_async16(sb + OPB + soff, B + (size_t)(n0 + row) * K + k0 + sc * 8);
    }
}

__device__ __forceinline__ void gemm_core(
    uint32_t sbase, const __half* A, const __half* B,
    int m0, int n0, int K, int tid, int wid, int lane,
    float acc[2][8][4])
{
    const int wm = wid >> 1;
    const int wn = wid & 1;
    const int NC = K / BK;

    prefetch16(sbase, 0, 0, A, B, m0, n0, K, tid); CP_COMMIT();

    const uint32_t lrow = (lane & 15);
    const uint32_t lcol = (lane >> 4) * 16;

    int stg_i = 0, stg_n = 1;
    for (int c = 0; c < NC; c++) {
        if (c + 1 < NC) {
            prefetch16(sbase, stg_n, c + 1, A, B, m0, n0, K, tid);
            CP_COMMIT();
            asm volatile("cp.async.wait_group 1;" ::: "memory");
        } else {
            asm volatile("cp.async.wait_group 0;" ::: "memory");
        }
        __syncthreads();

        const uint32_t stg = sbase + stg_i * STAGE16;
        const uint32_t aBase = stg + (wm * 32) * ROWB + lrow * ROWB + lcol;
        const uint32_t bBase = stg + OPB + (wn * 64) * ROWB + lrow * ROWB + lcol;

        #pragma unroll
        for (int kk = 0; kk < 4; kk++) {
            const uint32_t kb = kk * 32;
            uint32_t ah[2][4];
            #pragma unroll
            for (int mt = 0; mt < 2; mt++)
                ldmx4(ah[mt], aBase + mt * 16 * ROWB + kb);
            #pragma unroll
            for (int p = 0; p < 4; p++) {
                uint32_t bh[4];
                ldmx4(bh, bBase + p * 16 * ROWB + kb);
                #pragma unroll
                for (int mt = 0; mt < 2; mt++) {
                    mma_f16(acc[mt][2*p],   ah[mt], bh[0], bh[2]);
                    mma_f16(acc[mt][2*p+1], ah[mt], bh[1], bh[3]);
                }
            }
        }
        stg_i = stg_n;
        stg_n = (stg_n == 2) ? 0 : stg_n + 1;
    }
}

// ---- z-batched QKV projection: out fp16 head-permuted [B,H,S,hd] ----
__global__ __launch_bounds__(256, 2) void gemm_proj(
    const __half* __restrict__ A0, const __half* __restrict__ A1,
    const __half* __restrict__ A2,
    const float* __restrict__ b0c, const float* __restrict__ b1c,
    const float* __restrict__ b2c,
    __half* __restrict__ o0, __half* __restrict__ o1, __half* __restrict__ o2)
{
    extern __shared__ char smem[];
    const uint32_t sbase = smem_u32(smem);
    const int tid = threadIdx.x;
    const int wid = tid >> 5, lane = tid & 31;
    const int z = blockIdx.z;
    const int m0 = blockIdx.y * BM, n0 = blockIdx.x * BN;

    const __half* A  = (z == 0) ? A0 : (z == 1) ? A1 : A2;
    const float* bias = (z == 0) ? b0c : (z == 1) ? b1c : b2c;
    __half* Ch       = (z == 0) ? o0 : (z == 1) ? o1 : o2;
    const float scale = (z == 0) ? QKSCALE : 1.0f;

    float acc[2][8][4];
    #pragma unroll
    for (int i = 0; i < 2; i++)
        #pragma unroll
        for (int j = 0; j < 8; j++)
            #pragma unroll
            for (int x = 0; x < 4; x++) acc[i][j][x] = 0.f;

    const __half* B = (z == 0) ? g_Wq16 : (z == 1) ? g_Wk16 : g_Wv16;
    gemm_core(sbase, A, B, m0, n0, DMODEL, tid, wid, lane, acc);

    const int wm = wid >> 1, wn = wid & 1;
    const int rbase = m0 + wm * 32 + (lane >> 2);
    const int cbase = n0 + wn * 64 + (lane & 3) * 2;
    #pragma unroll
    for (int mt = 0; mt < 2; mt++) {
        #pragma unroll
        for (int nt = 0; nt < 8; nt++) {
            const int col = cbase + nt * 8;
            const float bz0 = bias[col], bz1 = bias[col + 1];
            #pragma unroll
            for (int h = 0; h < 2; h++) {
                const int row = rbase + mt * 16 + h * 8;
                float v0 = (acc[mt][nt][2*h]   + bz0) * scale;
                float v1 = (acc[mt][nt][2*h+1] + bz1) * scale;
                const int b = row >> 11, s = row & (SEQ - 1);
                const int hh = col >> 7, d = col & (HD - 1);
                *(__half2*)(Ch + (((size_t)b * NHEAD + hh) * SEQ + s) * HD + d)
                    = __floats2half2_rn(v0, v1);
            }
        }
    }
}

// ---- generic FF GEMM: fp16 out; mode 1 applies ReLU ----
__global__ __launch_bounds__(256, 2) void gemm_f16(
    const __half* __restrict__ A, const __half* __restrict__ B,
    const float* __restrict__ bias,
    __half* __restrict__ Ch, int M, int N, int K, int mode)
{
    extern __shared__ char smem[];
    const uint32_t sbase = smem_u32(smem);
    const int tid = threadIdx.x;
    const int wid = tid >> 5, lane = tid & 31;
    const int m0 = blockIdx.y * BM, n0 = blockIdx.x * BN;

    float acc[2][8][4];
    #pragma unroll
    for (int i = 0; i < 2; i++)
        #pragma unroll
        for (int j = 0; j < 8; j++)
            #pragma unroll
            for (int x = 0; x < 4; x++) acc[i][j][x] = 0.f;

    gemm_core(sbase, A, B, m0, n0, K, tid, wid, lane, acc);

    const int wm = wid >> 1, wn = wid & 1;
    const int rbase = m0 + wm * 32 + (lane >> 2);
    const int cbase = n0 + wn * 64 + (lane & 3) * 2;
    #pragma unroll
    for (int mt = 0; mt < 2; mt++) {
        #pragma unroll
        for (int nt = 0; nt < 8; nt++) {
            const int col = cbase + nt * 8;
            const float bz0 = bias[col], bz1 = bias[col + 1];
            #pragma unroll
            for (int h = 0; h < 2; h++) {
                const int row = rbase + mt * 16 + h * 8;
                float v0 = acc[mt][nt][2*h]   + bz0;
                float v1 = acc[mt][nt][2*h+1] + bz1;
                if (mode == 1) { v0 = fmaxf(v0, 0.f); v1 = fmaxf(v1, 0.f); }
                *(__half2*)(Ch + (size_t)row * N + col) = __floats2half2_rn(v0, v1);
            }
        }
    }
}

// =====================================================================
// fp16 flash attention: 128 thr / 4 warps / 64-q tiles, occ-2,
// swizzled tiles, NS=3 ring, ONE barrier per key-tile. mh out fp16.
// =====================================================================
#define ATHREADS 128
#define AQ 64
#define KTILE_B (64 * 256)             // 16384
#define STAGE_SZ (2 * KTILE_B)         // 32768
#define ANSTAGE 3
#define SKBASE KTILE_B                 // Q tile first: 16384
#define ATT_SMEM (SKBASE + ANSTAGE * STAGE_SZ)   // 114688

__device__ __forceinline__ void attn_prefetch(
    uint32_t sb, int stage, int kt,
    const __half* Kgb, const __half* Vgb, int tid)
{
    #pragma unroll
    for (int t = 0; t < 16; t++) {
        int idx = tid + t * ATHREADS;     // 0..2047
        int tensor = idx >> 10;           // 0: K, 1: V
        int row = (idx >> 4) & 63;
        int c   = idx & 15;
        uint32_t rel = row * 256 + (((uint32_t)c ^ (row & 7)) << 4);
        uint32_t dst = sb + SKBASE + stage * STAGE_SZ + tensor * KTILE_B + rel;
        const __half* src = (tensor ? Vgb : Kgb) + (size_t)(kt * 64 + row) * HD + c * 8;
        cp_async16(dst, src);
    }
}

__global__ __launch_bounds__(ATHREADS, 2) void attn_mma(
    const __half* __restrict__ Qg, const __half* __restrict__ Kg,
    const __half* __restrict__ Vg, __half* __restrict__ mh)
{
    extern __shared__ char smem[];
    const uint32_t sb = smem_u32(smem);
    const int tid = threadIdx.x;
    const int wid = tid >> 5, lane = tid & 31;
    const int qb = blockIdx.x;
    const int bh = blockIdx.y;
    const int b = bh >> 3, h = bh & 7;

    const __half* Qgb = Qg + ((size_t)bh * SEQ + qb * AQ) * HD;
    #pragma unroll
    for (int t = 0; t < 8; t++) {
        int idx = tid + t * ATHREADS;
        int row = idx >> 4, c = idx & 15;
        uint32_t rel = row * 256 + (((uint32_t)c ^ (row & 7)) << 4);
        cp_async16(sb + rel, Qgb + (size_t)row * HD + c * 8);
    }
    CP_COMMIT();
    const __half* Kgb = Kg + (size_t)bh * SEQ * HD;
    const __half* Vgb = Vg + (size_t)bh * SEQ * HD;
    attn_prefetch(sb, 0, 0, Kgb, Vgb, tid);
    CP_COMMIT();

    asm volatile("cp.async.wait_group 0;" ::: "memory");
    __syncthreads();

    const uint32_t lrow = lane & 15;
    const uint32_t hi16 = (lane >> 4) * 16;
    const uint32_t lanexor = (lrow & 7) << 4;

    uint32_t qf[8][4];
    {
        const uint32_t qrow = sb + (wid * 16 + lrow) * 256;
        #pragma unroll
        for (int ks = 0; ks < 8; ks++)
            ldmx4(qf[ks], qrow + (((uint32_t)(ks * 32) + hi16) ^ lanexor));
    }

    float oacc[16][4];
    #pragma unroll
    for (int i = 0; i < 16; i++)
        #pragma unroll
        for (int j = 0; j < 4; j++) oacc[i][j] = 0.f;
    float m0 = -1e30f, m1 = -1e30f, l0 = 0.f, l1 = 0.f;

    int stg_i = 0, stg_n = 1;
    for (int kt = 0; kt < 32; kt++) {
        if (kt + 1 < 32) {
            attn_prefetch(sb, stg_n, kt + 1, Kgb, Vgb, tid);
            CP_COMMIT();
            asm volatile("cp.async.wait_group 1;" ::: "memory");
        } else {
            asm volatile("cp.async.wait_group 0;" ::: "memory");
        }
        __syncthreads();

        const uint32_t kbase = sb + SKBASE + stg_i * STAGE_SZ;
        const uint32_t vbase = kbase + KTILE_B;

        float sacc[8][4];
        #pragma unroll
        for (int i = 0; i < 8; i++)
            #pragma unroll
            for (int j = 0; j < 4; j++) sacc[i][j] = 0.f;

        #pragma unroll
        for (int ks = 0; ks < 8; ks++) {
            const uint32_t colb = ((uint32_t)(ks * 32) + hi16) ^ lanexor;
            #pragma unroll
            for (int p = 0; p < 4; p++) {
                uint32_t kf[4];
                ldmx4(kf, kbase + (p * 16 + lrow) * 256 + colb);
                mma_f16(sacc[2*p],   qf[ks], kf[0], kf[2]);
                mma_f16(sacc[2*p+1], qf[ks], kf[1], kf[3]);
            }
        }

        float mx0 = -1e30f, mx1 = -1e30f;
        #pragma unroll
        for (int n = 0; n < 8; n++) {
            mx0 = fmaxf(mx0, fmaxf(sacc[n][0], sacc[n][1]));
            mx1 = fmaxf(mx1, fmaxf(sacc[n][2], sacc[n][3]));
        }
        mx0 = fmaxf(mx0, __shfl_xor_sync(0xffffffffu, mx0, 1));
        mx0 = fmaxf(mx0, __shfl_xor_sync(0xffffffffu, mx0, 2));
        mx1 = fmaxf(mx1, __shfl_xor_sync(0xffffffffu, mx1, 1));
        mx1 = fmaxf(mx1, __shfl_xor_sync(0xffffffffu, mx1, 2));
        const float mn0 = fmaxf(m0, mx0), mn1 = fmaxf(m1, mx1);
        const float a0 = __expf(m0 - mn0), a1 = __expf(m1 - mn1);
        m0 = mn0; m1 = mn1;
        float sum0 = 0.f, sum1 = 0.f;
        #pragma unroll
        for (int n = 0; n < 8; n++) {
            sacc[n][0] = __expf(sacc[n][0] - mn0);
            sacc[n][1] = __expf(sacc[n][1] - mn0);
            sacc[n][2] = __expf(sacc[n][2] - mn1);
            sacc[n][3] = __expf(sacc[n][3] - mn1);
            sum0 += sacc[n][0] + sacc[n][1];
            sum1 += sacc[n][2] + sacc[n][3];
        }
        sum0 += __shfl_xor_sync(0xffffffffu, sum0, 1);
        sum0 += __shfl_xor_sync(0xffffffffu, sum0, 2);
        sum1 += __shfl_xor_sync(0xffffffffu, sum1, 1);
        sum1 += __shfl_xor_sync(0xffffffffu, sum1, 2);
        l0 = l0 * a0 + sum0; l1 = l1 * a1 + sum1;
        #pragma unroll
        for (int i = 0; i < 16; i++) {
            oacc[i][0] *= a0; oacc[i][1] *= a0;
            oacc[i][2] *= a1; oacc[i][3] *= a1;
        }

        uint32_t ph[4][4];
        #pragma unroll
        for (int t = 0; t < 4; t++) {
            ph[t][0] = packh2(sacc[2*t][0],   sacc[2*t][1]);
            ph[t][1] = packh2(sacc[2*t][2],   sacc[2*t][3]);
            ph[t][2] = packh2(sacc[2*t+1][0], sacc[2*t+1][1]);
            ph[t][3] = packh2(sacc[2*t+1][2], sacc[2*t+1][3]);
        }

        #pragma unroll
        for (int t = 0; t < 4; t++) {
            const uint32_t vrow = vbase + (t * 16 + lrow) * 256;
            #pragma unroll
            for (int g = 0; g < 8; g++) {
                uint32_t vf[4];
                ldmx4t(vf, vrow + (((uint32_t)(g * 32) + hi16) ^ lanexor));
                mma_f16(oacc[2*g],   ph[t], vf[0], vf[1]);
                mma_f16(oacc[2*g+1], ph[t], vf[2], vf[3]);
            }
        }
        stg_i = stg_n;
        stg_n = (stg_n == 2) ? 0 : stg_n + 1;
    }

    const float inv0 = 1.f / l0, inv1 = 1.f / l1;
    const int row0 = qb * AQ + wid * 16 + (lane >> 2);
    __half* base0 = mh + ((size_t)b * SEQ + row0) * DMODEL + h * HD + (lane & 3) * 2;
    __half* base1 = base0 + 8 * DMODEL;
    #pragma unroll
    for (int nt = 0; nt < 16; nt++) {
        *(__half2*)(base0 + nt * 8) =
            __floats2half2_rn(oacc[nt][0] * inv0, oacc[nt][1] * inv0);
        *(__half2*)(base1 + nt * 8) =
            __floats2half2_rn(oacc[nt][2] * inv1, oacc[nt][3] * inv1);
    }
}

// =====================================================================
// LayerNorm (ddof=1, no eps) + residual — float4/half vectorized.
// XF16: x input fp16.  RES16: residual input fp16.  OUT16: output fp16.
// =====================================================================
template<int XF16, int RES16, int OUT16>
__global__ __launch_bounds__(256) void ln_res_k(
    const void* __restrict__ xv, const void* __restrict__ resv,
    void* __restrict__ outv)
{
    const int D = DMODEL;
    const size_t row = blockIdx.x;
    const int tid = threadIdx.x;

    float4 v4;
    if (XF16) {
        const __half2* xr = (const __half2*)((const __half*)xv + row * D) + tid * 2;
        float2 a = __half22float2(xr[0]);
        float2 c = __half22float2(xr[1]);
        v4 = make_float4(a.x, a.y, c.x, c.y);
    } else {
        v4 = ((const float4*)((const float*)xv + row * D))[tid];
    }
    float s  = v4.x + v4.y + v4.z + v4.w;
    float ss = fmaf(v4.x, v4.x, fmaf(v4.y, v4.y, fmaf(v4.z, v4.z, v4.w * v4.w)));

    #pragma unroll
    for (int off = 16; off > 0; off >>= 1) {
        s  += __shfl_xor_sync(0xffffffffu, s, off);
        ss += __shfl_xor_sync(0xffffffffu, ss, off);
    }
    __shared__ float sa[8], sbuf[8];
    int w = tid >> 5, l = tid & 31;
    if (l == 0) { sa[w] = s; sbuf[w] = ss; }
    __syncthreads();
    if (tid < 32) {
        s  = (l < 8) ? sa[l] : 0.f;
        ss = (l < 8) ? sbuf[l] : 0.f;
        #pragma unroll
        for (int off = 4; off > 0; off >>= 1) {
            s  += __shfl_xor_sync(0xffffffffu, s, off);
            ss += __shfl_xor_sync(0xffffffffu, ss, off);
        }
        if (l == 0) { sa[0] = s; sbuf[0] = ss; }
    }
    __syncthreads();
    s = sa[0]; ss = sbuf[0];

    float mean = s / (float)D;
    float var  = (ss - s * s / (float)D) / (float)(D - 1);
    float rstd = rsqrtf(var);

    float4 r4;
    if (RES16) {
        const __half2* rr = (const __half2*)((const __half*)resv + row * D) + tid * 2;
        float2 a = __half22float2(rr[0]);
        float2 c = __half22float2(rr[1]);
        r4 = make_float4(a.x, a.y, c.x, c.y);
    } else {
        r4 = ((const float4*)((const float*)resv + row * D))[tid];
    }
    float4 o4;
    o4.x = r4.x + (v4.x - mean) * rstd;
    o4.y = r4.y + (v4.y - mean) * rstd;
    o4.z = r4.z + (v4.z - mean) * rstd;
    o4.w = r4.w + (v4.w - mean) * rstd;
    if (OUT16) {
        __half2* hp = (__half2*)((__half*)outv + row * D + tid * 4);
        hp[0] = __floats2half2_rn(o4.x, o4.y);
        hp[1] = __floats2half2_rn(o4.z, o4.w);
    } else {
        ((float4*)((float*)outv + row * D))[tid] = o4;
    }
}

// =====================================================================
extern "C" void kernel_launch(void* const* d_in, const int* in_sizes, int n_in,
                              void* d_out, int out_size)
{
    const float* q  = (const float*)d_in[0];
    const float* k  = (const float*)d_in[1];
    const float* v  = (const float*)d_in[2];
    const float* Wq = (const float*)d_in[3];
    const float* bq = (const float*)d_in[4];
    const float* Wk = (const float*)d_in[5];
    const float* bk = (const float*)d_in[6];
    const float* Wv = (const float*)d_in[7];
    const float* bv = (const float*)d_in[8];
    const float* W1 = (const float*)d_in[9];
    const float* b1 = (const float*)d_in[10];
    const float* W2 = (const float*)d_in[11];
    const float* b2 = (const float*)d_in[12];

    __half *tmp16, *mh16, *res116, *A16, *F16, *W1t, *W2t, *Wq16, *Wk16, *Wv16, *Qh, *Kh, *Vh;
    cudaGetSymbolAddress((void**)&tmp16,  g_tmp16);
    cudaGetSymbolAddress((void**)&mh16,   g_mh16);
    cudaGetSymbolAddress((void**)&res116, g_res116);
    cudaGetSymbolAddress((void**)&A16,    g_A16);
    cudaGetSymbolAddress((void**)&F16,    g_F16);
    cudaGetSymbolAddress((void**)&W1t,    g_W1t);
    cudaGetSymbolAddress((void**)&W2t,    g_W2t);
    cudaGetSymbolAddress((void**)&Wq16,   g_Wq16);
    cudaGetSymbolAddress((void**)&Wk16,   g_Wk16);
    cudaGetSymbolAddress((void**)&Wv16,   g_Wv16);
    cudaGetSymbolAddress((void**)&Qh,     g_Qh);
    cudaGetSymbolAddress((void**)&Kh,     g_Kh);
    cudaGetSymbolAddress((void**)&Vh,     g_Vh);

    // q16 / k16 staged in first/second half of F16 (free until FF1 output)
    __half* v16 = A16;
    __half* q16 = F16;
    __half* k16 = F16 + (size_t)MROWS * DMODEL;

    cudaFuncSetAttribute(gemm_proj,
                         cudaFuncAttributeMaxDynamicSharedMemorySize, GEMM16_SMEM);
    cudaFuncSetAttribute(gemm_f16,
                         cudaFuncAttributeMaxDynamicSharedMemorySize, GEMM16_SMEM);
    cudaFuncSetAttribute(attn_mma,
                         cudaFuncAttributeMaxDynamicSharedMemorySize, ATT_SMEM);

    dim3 blk(256);
    dim3 gProj(DMODEL / BN, MROWS / BM, 3);   // (8, 64, 3)
    dim3 gFF1(DFF / BN, MROWS / BM);          // (32, 64)
    dim3 gFF2(DMODEL / BN, MROWS / BM);       // (8, 64)

    // all format conversions, one launch
    conv_wt_all<<<CW_BLOCKS, blk>>>(v, q, k, v16, q16, k16,
                                    Wq, Wk, Wv, W1, W2,
                                    Wq16, Wk16, Wv16, W1t, W2t);

    // Encoder calls multihead(v, q, k): Q-in=v, K-in=q, V-in=k
    gemm_proj<<<gProj, blk, GEMM16_SMEM>>>(v16, q16, k16, bq, bk, bv, Qh, Kh, Vh);

    attn_mma<<<dim3(SEQ / AQ, BATCH * NHEAD), dim3(ATHREADS), ATT_SMEM>>>(Qh, Kh, Vh, mh16);

    // res1 = q + LN(mh) — stored ONCE, fp16 (doubles as FF1 input)
    ln_res_k<1, 0, 1><<<MROWS, blk>>>(mh16, q, res116);

    gemm_f16<<<gFF1, blk, GEMM16_SMEM>>>(res116, W1t, b1, F16,
                                         MROWS, DFF, DMODEL, 1);
    gemm_f16<<<gFF2, blk, GEMM16_SMEM>>>(F16, W2t, b2, tmp16,
                                         MROWS, DMODEL, DFF, 0);

    // out = res1 + LN(ff)
    ln_res_k<1, 1, 0><<<MROWS, blk>>>(tmp16, res116, (float*)d_out);
}